// round 9
// baseline (speedup 1.0000x reference)
#include <cuda_runtime.h>
#include <cuda_fp16.h>
#include <cstdint>
#include <cstddef>

// Problem constants
#define E_DIM 1024
#define S_LEN 1024
#define B_SZ 4
#define NH 16
#define HD 64
#define FF_DIM 4096
#define M_ROWS (B_SZ * S_LEN)   // 4096

// ---------------- scratch (static device globals; no allocation) ----------------
__device__ float g_tmp[M_ROWS * E_DIM];          // attn_out, later (x1+ff)
__device__ float g_x1[M_ROWS * E_DIM];
__device__ float g_pb[S_LEN * S_LEN];

// fp16 activations
__device__ __half g_qkvgf[M_ROWS * 4096];        // [q|k|v|gate] fp16
__device__ __half g_xf[M_ROWS * E_DIM];
__device__ __half g_ctxf[M_ROWS * E_DIM];
__device__ __half g_x1f[M_ROWS * E_DIM];
__device__ __half g_h1f[(size_t)M_ROWS * FF_DIM];

// fp16 weights in ORIGINAL [K,N] layout (no transpose; B fed via ldmatrix.trans)
__device__ __half g_wqkvg[1024 * 4096];          // cols: [Wq|Wk|Wv|Wg]
__device__ __half g_wo[1024 * 1024];
__device__ __half g_wff[1024 * 8192];            // cols interleaved: 2n = Wf1_n, 2n+1 = Wfg_n
__device__ __half g_wf2[4096 * 1024];

__device__ float g_bias_qkvg[4096];
__device__ float g_bias_ff[8192];                 // interleaved bf1/bfg

#define L2E 1.4426950408889634f

// =================== PTX helpers (baseline sm_80+ features only) ===================
__device__ __forceinline__ uint32_t smem_u32(const void* p) {
    uint32_t a;
    asm("{ .reg .u64 t; cvta.to.shared.u64 t, %1; cvt.u32.u64 %0, t; }" : "=r"(a) : "l"(p));
    return a;
}
__device__ __forceinline__ void cp16(uint32_t dst, const void* src) {
    asm volatile("cp.async.cg.shared.global [%0], [%1], 16;" :: "r"(dst), "l"(src));
}
#define CP_COMMIT() asm volatile("cp.async.commit_group;" ::: "memory")
#define CP_WAIT1()  asm volatile("cp.async.wait_group 1;" ::: "memory")
#define CP_WAIT0()  asm volatile("cp.async.wait_group 0;" ::: "memory")

__device__ __forceinline__ void ldm_x4(uint32_t& r0, uint32_t& r1, uint32_t& r2,
                                       uint32_t& r3, uint32_t addr) {
    asm volatile("ldmatrix.sync.aligned.m8n8.x4.shared.b16 {%0,%1,%2,%3}, [%4];"
                 : "=r"(r0), "=r"(r1), "=r"(r2), "=r"(r3) : "r"(addr));
}
__device__ __forceinline__ void ldm_x4t(uint32_t& r0, uint32_t& r1, uint32_t& r2,
                                        uint32_t& r3, uint32_t addr) {
    asm volatile("ldmatrix.sync.aligned.m8n8.x4.trans.shared.b16 {%0,%1,%2,%3}, [%4];"
                 : "=r"(r0), "=r"(r1), "=r"(r2), "=r"(r3) : "r"(addr));
}
// fp16 MMA
__device__ __forceinline__ void mma16816h(float* c, const uint32_t* a,
                                          uint32_t b0, uint32_t b1) {
    asm volatile(
        "mma.sync.aligned.m16n8k16.row.col.f32.f16.f16.f32 "
        "{%0,%1,%2,%3}, {%4,%5,%6,%7}, {%8,%9}, {%0,%1,%2,%3};"
        : "+f"(c[0]), "+f"(c[1]), "+f"(c[2]), "+f"(c[3])
        : "r"(a[0]), "r"(a[1]), "r"(a[2]), "r"(a[3]), "r"(b0), "r"(b1));
}
__device__ __forceinline__ float ex2f(float x) {
    float y;
    asm("ex2.approx.ftz.f32 %0, %1;" : "=f"(y) : "f"(x));
    return y;
}

// =================== HMMA GEMM (fp16, B via trans-ldmatrix from [K,N]) ===================
// A: [M,K] fp16. W: [K,N] fp16 (original layout).
// MODE 0: C[M,N] fp32 = A@W + bias
// MODE 1: SwiGLU: Of[M,N/2] fp16 = (c_even+b_even) * sigmoid(c_odd+b_odd)
// MODE 2: C = A@W + bias + R
// MODE 3: Of[M,N] fp16 = A@W + bias
// smem stage: A[128r x 80B] @0 (10240B), B[32k x 272B] @10240 (8704B); 3 stages.
#define B_SOFF 10240
#define STAGE_BYTES 18944
#define GEMM_SMEM (3 * STAGE_BYTES)

template <int MODE>
__global__ __launch_bounds__(256, 2)
void hmma_gemm(const __half* __restrict__ Af, const __half* __restrict__ W,
               const float* __restrict__ bias, float* __restrict__ C,
               __half* __restrict__ Of, const float* __restrict__ R,
               int M, int N, int K) {
    extern __shared__ char smem[];
    const uint32_t sb = smem_u32(smem);
    const int tid = threadIdx.x;
    const int wid = tid >> 5, lane = tid & 31;
    const int brow = blockIdx.y * 128, bcol = blockIdx.x * 128;
    const int wm = (wid >> 2) * 64, wn = (wid & 3) * 32;
    const int nst = K >> 5;

    // A: 512 chunks (128 rows x 4); B: 512 chunks (32 rows x 16)
    const int ar0 = tid >> 2, ar1 = (tid + 256) >> 2;
    const int ac0 = tid & 3,  ac1 = (tid + 256) & 3;
    const uint32_t aso0 = (uint32_t)(ar0 * 80 + ac0 * 16);
    const uint32_t aso1 = (uint32_t)(ar1 * 80 + ac1 * 16);
    const int br0 = tid >> 4, br1 = (tid + 256) >> 4;
    const int bc0 = tid & 15, bc1 = (tid + 256) & 15;
    const uint32_t bso0 = (uint32_t)(B_SOFF + br0 * 272 + bc0 * 16);
    const uint32_t bso1 = (uint32_t)(B_SOFF + br1 * 272 + bc1 * 16);

#define LOAD_STAGE(s, buf) do {                                               \
        const uint32_t stb_ = sb + (buf) * STAGE_BYTES;                       \
        cp16(stb_ + aso0, Af + (size_t)(brow + ar0) * K + (s) * 32 + ac0 * 8);\
        cp16(stb_ + aso1, Af + (size_t)(brow + ar1) * K + (s) * 32 + ac1 * 8);\
        cp16(stb_ + bso0, W + (size_t)((s) * 32 + br0) * N + bcol + bc0 * 8); \
        cp16(stb_ + bso1, W + (size_t)((s) * 32 + br1) * N + bcol + bc1 * 8); \
    } while (0)

    float acc[4][4][4];
#pragma unroll
    for (int i = 0; i < 4; i++)
#pragma unroll
        for (int j = 0; j < 4; j++)
#pragma unroll
            for (int r = 0; r < 4; r++) acc[i][j][r] = 0.f;

    LOAD_STAGE(0, 0); CP_COMMIT();
    LOAD_STAGE(1, 1); CP_COMMIT();

    const uint32_t a_lrow = (uint32_t)(lane & 15);
    const uint32_t a_koff = (uint32_t)((lane & 16) >> 1);
    const uint32_t b_krow = (uint32_t)((lane & 7) + (lane & 8));   // k-row within k16
    const uint32_t b_noff2 = (uint32_t)((lane & 16) >> 1) * 2;     // +16B for upper half

    for (int s = 0; s < nst; s++) {
        CP_WAIT1();
        __syncthreads();
        if (s + 2 < nst) LOAD_STAGE(s + 2, (s + 2) % 3);
        CP_COMMIT();
        const uint32_t stb = sb + (uint32_t)(s % 3) * STAGE_BYTES;

#pragma unroll
        for (int kk = 0; kk < 32; kk += 16) {
            uint32_t bf[2][4];
#pragma unroll
            for (int ni = 0; ni < 2; ni++) {
                const uint32_t addr = stb + B_SOFF +
                    (uint32_t)(kk + b_krow) * 272 + (uint32_t)(wn + ni * 16) * 2 + b_noff2;
                ldm_x4t(bf[ni][0], bf[ni][1], bf[ni][2], bf[ni][3], addr);
            }
            const uint32_t akcol = (uint32_t)kk + a_koff;
#pragma unroll
            for (int mi = 0; mi < 4; mi++) {
                uint32_t a[4];
                const uint32_t addr = stb + (uint32_t)(wm + mi * 16 + a_lrow) * 80 + akcol * 2;
                ldm_x4(a[0], a[1], a[2], a[3], addr);
#pragma unroll
                for (int nj = 0; nj < 4; nj++) {
                    const int g = nj >> 1, p = (nj & 1) * 2;
                    mma16816h(acc[mi][nj], a, bf[g][p], bf[g][p + 1]);
                }
            }
        }
    }

    const int qr = lane >> 2, qc = (lane & 3) * 2;
#pragma unroll
    for (int mi = 0; mi < 4; mi++) {
        const size_t gr = (size_t)(brow + wm + mi * 16 + qr);
#pragma unroll
        for (int nj = 0; nj < 4; nj++) {
            const int gc = bcol + wn + nj * 8 + qc;
            const float2 b2 = *(const float2*)(bias + gc);
            if (MODE == 0 || MODE == 2) {
                float2 o0, o1;
                o0.x = acc[mi][nj][0] + b2.x;
                o0.y = acc[mi][nj][1] + b2.y;
                o1.x = acc[mi][nj][2] + b2.x;
                o1.y = acc[mi][nj][3] + b2.y;
                if (MODE == 2) {
                    const float2 r0 = *(const float2*)(R + gr * N + gc);
                    const float2 r1 = *(const float2*)(R + (gr + 8) * N + gc);
                    o0.x += r0.x; o0.y += r0.y;
                    o1.x += r1.x; o1.y += r1.y;
                }
                *(float2*)(C + gr * N + gc)       = o0;
                *(float2*)(C + (gr + 8) * N + gc) = o1;
            } else if (MODE == 3) {
                const __half2 o0 = __floats2half2_rn(acc[mi][nj][0] + b2.x,
                                                     acc[mi][nj][1] + b2.y);
                const __half2 o1 = __floats2half2_rn(acc[mi][nj][2] + b2.x,
                                                     acc[mi][nj][3] + b2.y);
                *(__half2*)(Of + gr * N + gc)       = o0;
                *(__half2*)(Of + (gr + 8) * N + gc) = o1;
            } else {
                const float h1v0 = acc[mi][nj][0] + b2.x;
                const float hg0  = acc[mi][nj][1] + b2.y;
                const float h1v1 = acc[mi][nj][2] + b2.x;
                const float hg1  = acc[mi][nj][3] + b2.y;
                const float o0 = h1v0 / (1.f + ex2f(-hg0 * L2E));
                const float o1 = h1v1 / (1.f + ex2f(-hg1 * L2E));
                const size_t co = (size_t)(gc >> 1);
                Of[gr * (N >> 1) + co]       = __float2half(o0);
                Of[(gr + 8) * (N >> 1) + co] = __float2half(o1);
            }
        }
    }
#undef LOAD_STAGE
}

// =================== fp16 flash attention ===================
#define ATT_Q 0
#define ATT_KV0 18432
#define ATT_KV1 36864
#define ATT_SMEM 55296

__global__ __launch_bounds__(256, 2)
void attention_f16(const __half* __restrict__ QKVF, const float* __restrict__ PB,
                   __half* __restrict__ CTXF) {
    extern __shared__ char smem[];
    const uint32_t sbase = smem_u32(smem);
    const int tid = threadIdx.x;
    const int wid = tid >> 5, lane = tid & 31;
    const int b = blockIdx.y >> 4, h = blockIdx.y & 15;
    const int q0 = blockIdx.x * 128;
    const int wr = wid * 16;

#pragma unroll
    for (int it = 0; it < 4; it++) {
        const int c = tid + it * 256;
        const int r = c >> 3, co = c & 7;
        cp16(sbase + ATT_Q + (uint32_t)(r * 144 + co * 16),
             QKVF + (((size_t)b << 10) + q0 + r) * 4096 + h * 64 + co * 8);
    }
#define LOAD_KV(kt, bufoff) do {                                              \
        _Pragma("unroll")                                                     \
        for (int it = 0; it < 4; it++) {                                      \
            const int c = tid + it * 256;                                     \
            const int kv = c >> 9;                                            \
            const int cc = c & 511;                                           \
            const int r = cc >> 3, co = cc & 7;                               \
            cp16(sbase + (bufoff) + (uint32_t)(kv * 9216 + r * 144 + co * 16),\
                 QKVF + (((size_t)b << 10) + (kt) * 64 + r) * 4096 +          \
                     (1 + kv) * 1024 + h * 64 + co * 8);                      \
        }                                                                     \
    } while (0)

    LOAD_KV(0, ATT_KV0);
    CP_COMMIT();

    const uint32_t a_lrow = (uint32_t)(lane & 15);
    const uint32_t a_koff2 = (uint32_t)((lane & 16) >> 1) * 2;
    const uint32_t b_lrow = (uint32_t)((lane & 7) + ((lane & 16) >> 1));
    const uint32_t b_koff2 = (uint32_t)(lane & 8) * 2;
    const uint32_t v_row = (uint32_t)((lane & 7) + (lane & 8));
    const uint32_t v_col2 = (uint32_t)((lane & 16) >> 1) * 2;

    const int qr = lane >> 2, qc = (lane & 3) * 2;
    float m0 = -1e30f, m1 = -1e30f, l0 = 0.f, l1 = 0.f;
    float oacc[8][4];
#pragma unroll
    for (int nt = 0; nt < 8; nt++)
#pragma unroll
        for (int e = 0; e < 4; e++) oacc[nt][e] = 0.f;

    for (int kt = 0; kt < 16; kt++) {
        CP_WAIT0();
        __syncthreads();
        const uint32_t kvb = (kt & 1) ? ATT_KV1 : ATT_KV0;
        if (kt < 15) LOAD_KV(kt + 1, (kt & 1) ? ATT_KV0 : ATT_KV1);
        CP_COMMIT();

        float sa[8][4];
#pragma unroll
        for (int nt = 0; nt < 8; nt++)
#pragma unroll
            for (int e = 0; e < 4; e++) sa[nt][e] = 0.f;

#pragma unroll
        for (int k16 = 0; k16 < 4; k16++) {
            uint32_t q[4];
            const uint32_t qaddr =
                sbase + ATT_Q + (uint32_t)(wr + a_lrow) * 144 + k16 * 32 + a_koff2;
            ldm_x4(q[0], q[1], q[2], q[3], qaddr);
#pragma unroll
            for (int ntp = 0; ntp < 4; ntp++) {
                uint32_t kf[4];
                const uint32_t kaddr =
                    sbase + kvb + (uint32_t)(ntp * 16 + b_lrow) * 144 + k16 * 32 + b_koff2;
                ldm_x4(kf[0], kf[1], kf[2], kf[3], kaddr);
                mma16816h(sa[2 * ntp],     q, kf[0], kf[1]);
                mma16816h(sa[2 * ntp + 1], q, kf[2], kf[3]);
            }
        }

        const size_t r0g = (size_t)(q0 + wr + qr);
        const size_t pb0 = r0g * 1024 + kt * 64 + qc;
        const size_t pb1 = (r0g + 8) * 1024 + kt * 64 + qc;
#pragma unroll
        for (int nt = 0; nt < 8; nt++) {
            const float2 p0 = *(const float2*)&PB[pb0 + nt * 8];
            const float2 p1 = *(const float2*)&PB[pb1 + nt * 8];
            sa[nt][0] = sa[nt][0] * 0.125f + p0.x;
            sa[nt][1] = sa[nt][1] * 0.125f + p0.y;
            sa[nt][2] = sa[nt][2] * 0.125f + p1.x;
            sa[nt][3] = sa[nt][3] * 0.125f + p1.y;
        }

        float tm0 = -1e30f, tm1 = -1e30f;
#pragma unroll
        for (int nt = 0; nt < 8; nt++) {
            tm0 = fmaxf(tm0, fmaxf(sa[nt][0], sa[nt][1]));
            tm1 = fmaxf(tm1, fmaxf(sa[nt][2], sa[nt][3]));
        }
        tm0 = fmaxf(tm0, __shfl_xor_sync(0xffffffffu, tm0, 1));
        tm0 = fmaxf(tm0, __shfl_xor_sync(0xffffffffu, tm0, 2));
        tm1 = fmaxf(tm1, __shfl_xor_sync(0xffffffffu, tm1, 1));
        tm1 = fmaxf(tm1, __shfl_xor_sync(0xffffffffu, tm1, 2));
        const float mn0 = fmaxf(m0, tm0), mn1 = fmaxf(m1, tm1);
        const float cr0 = ex2f((m0 - mn0) * L2E), cr1 = ex2f((m1 - mn1) * L2E);
        m0 = mn0; m1 = mn1;

        float rs0 = 0.f, rs1 = 0.f;
#pragma unroll
        for (int nt = 0; nt < 8; nt++) {
            sa[nt][0] = ex2f((sa[nt][0] - mn0) * L2E);
            sa[nt][1] = ex2f((sa[nt][1] - mn0) * L2E);
            sa[nt][2] = ex2f((sa[nt][2] - mn1) * L2E);
            sa[nt][3] = ex2f((sa[nt][3] - mn1) * L2E);
            rs0 += sa[nt][0] + sa[nt][1];
            rs1 += sa[nt][2] + sa[nt][3];
        }
        rs0 += __shfl_xor_sync(0xffffffffu, rs0, 1);
        rs0 += __shfl_xor_sync(0xffffffffu, rs0, 2);
        rs1 += __shfl_xor_sync(0xffffffffu, rs1, 1);
        rs1 += __shfl_xor_sync(0xffffffffu, rs1, 2);
        l0 = l0 * cr0 + rs0;
        l1 = l1 * cr1 + rs1;
#pragma unroll
        for (int nt = 0; nt < 8; nt++) {
            oacc[nt][0] *= cr0; oacc[nt][1] *= cr0;
            oacc[nt][2] *= cr1; oacc[nt][3] *= cr1;
        }

#pragma unroll
        for (int j = 0; j < 4; j++) {
            uint32_t pha[4];
            {
                const float* s0 = sa[2 * j];
                const float* s1 = sa[2 * j + 1];
                const __half2 a0 = __floats2half2_rn(s0[0], s0[1]);
                const __half2 a1 = __floats2half2_rn(s0[2], s0[3]);
                const __half2 a2 = __floats2half2_rn(s1[0], s1[1]);
                const __half2 a3 = __floats2half2_rn(s1[2], s1[3]);
                pha[0] = *(const uint32_t*)&a0;
                pha[1] = *(const uint32_t*)&a1;
                pha[2] = *(const uint32_t*)&a2;
                pha[3] = *(const uint32_t*)&a3;
            }
#pragma unroll
            for (int ntp = 0; ntp < 4; ntp++) {
                uint32_t vf[4];
                const uint32_t vaddr = sbase + kvb + 9216 +
                    (uint32_t)(j * 16 + v_row) * 144 + (uint32_t)(ntp * 16) * 2 + v_col2;
                ldm_x4t(vf[0], vf[1], vf[2], vf[3], vaddr);
                mma16816h(oacc[2 * ntp],     pha, vf[0], vf[1]);
                mma16816h(oacc[2 * ntp + 1], pha, vf[2], vf[3]);
            }
        }
        __syncthreads();
    }

    const float inv0 = 1.f / l0, inv1 = 1.f / l1;
    const size_t cr0 = (size_t)((b << 10) + q0 + wr + qr);
    const size_t colb = (size_t)(h * 64 + qc);
#pragma unroll
    for (int nt = 0; nt < 8; nt++) {
        const __half2 h2a = __floats2half2_rn(oacc[nt][0] * inv0, oacc[nt][1] * inv0);
        const __half2 h2b = __floats2half2_rn(oacc[nt][2] * inv1, oacc[nt][3] * inv1);
        *(__half2*)(CTXF + cr0 * 1024 + colb + nt * 8)       = h2a;
        *(__half2*)(CTXF + (cr0 + 8) * 1024 + colb + nt * 8) = h2b;
    }
#undef LOAD_KV
}

// =================== weight converts (no transpose; coalesced both sides) ===================
// straight fp32 -> fp16 with column packing into a wider row
__global__ __launch_bounds__(256)
void conv_w(const float* __restrict__ W, __half* __restrict__ T,
            int N, int outN, int coloff) {
    const size_t i = ((size_t)blockIdx.x * 256 + threadIdx.x) * 4;
    const size_t r = i / (size_t)N;
    const int c = (int)(i % (size_t)N);
    const float4 v = *(const float4*)(W + i);
    uint2 o;
    const __half2 a = __floats2half2_rn(v.x, v.y);
    const __half2 b = __floats2half2_rn(v.z, v.w);
    o.x = *(const uint32_t*)&a;
    o.y = *(const uint32_t*)&b;
    *(uint2*)(T + r * (size_t)outN + coloff + c) = o;
}

// interleave two [K,N] matrices column-wise: out[k][2n]=A[k][n], out[k][2n+1]=B[k][n]
__global__ __launch_bounds__(256)
void conv_wff(const float* __restrict__ W1, const float* __restrict__ Wg,
              __half* __restrict__ T) {
    const size_t i = ((size_t)blockIdx.x * 256 + threadIdx.x) * 4;   // over K*4096
    const float4 a = *(const float4*)(W1 + i);
    const float4 g = *(const float4*)(Wg + i);
    uint4 o;
    const __half2 p0 = __floats2half2_rn(a.x, g.x);
    const __half2 p1 = __floats2half2_rn(a.y, g.y);
    const __half2 p2 = __floats2half2_rn(a.z, g.z);
    const __half2 p3 = __floats2half2_rn(a.w, g.w);
    o.x = *(const uint32_t*)&p0;
    o.y = *(const uint32_t*)&p1;
    o.z = *(const uint32_t*)&p2;
    o.w = *(const uint32_t*)&p3;
    *(uint4*)(T + i * 2) = o;
}

__global__ __launch_bounds__(256)
void conv_half(const float* __restrict__ X, __half* __restrict__ Xf) {
    const size_t i = ((size_t)blockIdx.x * 256 + threadIdx.x) * 4;
    const float4 v = *(const float4*)(X + i);
    uint2 o;
    const __half2 a = __floats2half2_rn(v.x, v.y);
    const __half2 b = __floats2half2_rn(v.z, v.w);
    o.x = *(const uint32_t*)&a;
    o.y = *(const uint32_t*)&b;
    *(uint2*)(Xf + i) = o;
}

__global__ void pack_bias(const float* bq, const float* bk, const float* bv,
                          const float* bg, const float* bf1, const float* bfg,
                          float* outq, float* outf) {
    const int i = blockIdx.x * 256 + threadIdx.x;   // 0..12287
    if (i < 1024) outq[i] = bq[i];
    else if (i < 2048) outq[i] = bk[i - 1024];
    else if (i < 3072) outq[i] = bv[i - 2048];
    else if (i < 4096) outq[i] = bg[i - 3072];
    else if (i < 8192) outf[2 * (i - 4096)] = bf1[i - 4096];
    else outf[2 * (i - 8192) + 1] = bfg[i - 8192];
}

__global__ __launch_bounds__(256)
void posbias_kernel(const float* __restrict__ pe, float* __restrict__ pb) {
    const size_t i = (size_t)blockIdx.x * 256 + threadIdx.x;
    const float4 a = *(const float4*)&pe[i * 8];
    const float4 b = *(const float4*)&pe[i * 8 + 4];
    pb[i] = (a.x + a.y + a.z + a.w + b.x + b.y + b.z + b.w) * 0.125f;
}

// ---------------- LN1 ----------------
__global__ __launch_bounds__(256)
void ln1_kernel(const float* __restrict__ x, const float* __restrict__ attn,
                const __half* __restrict__ qkvgf, const float* __restrict__ gw,
                const float* __restrict__ gb, float* __restrict__ x1,
                __half* __restrict__ x1f) {
    const size_t base = (size_t)blockIdx.x * E_DIM;
    const size_t gbase = (size_t)blockIdx.x * 4096 + 3072;
    const int t = threadIdx.x;
    float vals[4];
    float s = 0.f, s2 = 0.f;
#pragma unroll
    for (int i = 0; i < 4; i++) {
        const int c = t + i * 256;
        const float gp = __half2float(qkvgf[gbase + c]);
        const float sg = 1.f / (1.f + __expf(-gp));
        const float val = x[base + c] + attn[base + c] * sg;
        vals[i] = val; s += val; s2 += val * val;
    }
    __shared__ float rsm[8], rs2[8];
#pragma unroll
    for (int o = 16; o; o >>= 1) {
        s  += __shfl_xor_sync(0xffffffffu, s,  o);
        s2 += __shfl_xor_sync(0xffffffffu, s2, o);
    }
    if ((t & 31) == 0) { rsm[t >> 5] = s; rs2[t >> 5] = s2; }
    __syncthreads();
    float S = 0.f, S2 = 0.f;
#pragma unroll
    for (int i = 0; i < 8; i++) { S += rsm[i]; S2 += rs2[i]; }
    const float mean = S * (1.f / E_DIM);
    const float var = S2 * (1.f / E_DIM) - mean * mean;
    const float inv = rsqrtf(var + 1e-6f);
#pragma unroll
    for (int i = 0; i < 4; i++) {
        const int c = t + i * 256;
        const float v = (vals[i] - mean) * inv * gw[c] + gb[c];
        x1[base + c] = v;
        x1f[base + c] = __float2half(v);
    }
}

// ---------------- LN2 (input already contains x1+ff residual) ----------------
__global__ __launch_bounds__(256)
void ln2_kernel(const float* __restrict__ ff,
                const float* __restrict__ gw, const float* __restrict__ gb,
                float* __restrict__ out) {
    const size_t base = (size_t)blockIdx.x * E_DIM;
    const int t = threadIdx.x;
    float vals[4];
    float s = 0.f, s2 = 0.f;
#pragma unroll
    for (int i = 0; i < 4; i++) {
        const int c = t + i * 256;
        const float val = ff[base + c];
        vals[i] = val; s += val; s2 += val * val;
    }
    __shared__ float rsm[8], rs2[8];
#pragma unroll
    for (int o = 16; o; o >>= 1) {
        s  += __shfl_xor_sync(0xffffffffu, s,  o);
        s2 += __shfl_xor_sync(0xffffffffu, s2, o);
    }
    if ((t & 31) == 0) { rsm[t >> 5] = s; rs2[t >> 5] = s2; }
    __syncthreads();
    float S = 0.f, S2 = 0.f;
#pragma unroll
    for (int i = 0; i < 8; i++) { S += rsm[i]; S2 += rs2[i]; }
    const float mean = S * (1.f / E_DIM);
    const float var = S2 * (1.f / E_DIM) - mean * mean;
    const float inv = rsqrtf(var + 1e-6f);
#pragma unroll
    for (int i = 0; i < 4; i++) {
        const int c = t + i * 256;
        out[base + c] = (vals[i] - mean) * inv * gw[c] + gb[c];
    }
}

// =================== launch ===================
extern "C" void kernel_launch(void* const* d_in, const int* in_sizes, int n_in,
                              void* d_out, int out_size) {
    const float* x   = (const float*)d_in[0];
    const float* pe  = (const float*)d_in[1];
    const float* Wq  = (const float*)d_in[2];
    const float* bq  = (const float*)d_in[3];
    const float* Wk  = (const float*)d_in[4];
    const float* bk  = (const float*)d_in[5];
    const float* Wv  = (const float*)d_in[6];
    const float* bv  = (const float*)d_in[7];
    const float* Wo  = (const float*)d_in[8];
    const float* bo  = (const float*)d_in[9];
    const float* Wg  = (const float*)d_in[10];
    const float* bg  = (const float*)d_in[11];
    const float* Wf1 = (const float*)d_in[12];
    const float* bf1 = (const float*)d_in[13];
    const float* Wfg = (const float*)d_in[14];
    const float* bfg = (const float*)d_in[15];
    const float* Wf2 = (const float*)d_in[16];
    const float* bf2 = (const float*)d_in[17];
    const float* l1g = (const float*)d_in[18];
    const float* l1b = (const float*)d_in[19];
    const float* l2g = (const float*)d_in[20];
    const float* l2b = (const float*)d_in[21];
    float* out = (float*)d_out;

    float *tmp, *x1, *pb, *biasq, *biasf;
    __half *qkvgf, *xf, *ctxf, *x1f, *h1f;
    __half *wq, *wo, *wff, *w2;
    cudaGetSymbolAddress((void**)&tmp, g_tmp);
    cudaGetSymbolAddress((void**)&x1, g_x1);
    cudaGetSymbolAddress((void**)&pb, g_pb);
    cudaGetSymbolAddress((void**)&biasq, g_bias_qkvg);
    cudaGetSymbolAddress((void**)&biasf, g_bias_ff);
    cudaGetSymbolAddress((void**)&qkvgf, g_qkvgf);
    cudaGetSymbolAddress((void**)&xf, g_xf);
    cudaGetSymbolAddress((void**)&ctxf, g_ctxf);
    cudaGetSymbolAddress((void**)&x1f, g_x1f);
    cudaGetSymbolAddress((void**)&h1f, g_h1f);
    cudaGetSymbolAddress((void**)&wq, g_wqkvg);
    cudaGetSymbolAddress((void**)&wo, g_wo);
    cudaGetSymbolAddress((void**)&wff, g_wff);
    cudaGetSymbolAddress((void**)&w2, g_wf2);

    cudaFuncSetAttribute(attention_f16,
                         cudaFuncAttributeMaxDynamicSharedMemorySize, ATT_SMEM);
    cudaFuncSetAttribute(hmma_gemm<0>,
                         cudaFuncAttributeMaxDynamicSharedMemorySize, GEMM_SMEM);
    cudaFuncSetAttribute(hmma_gemm<1>,
                         cudaFuncAttributeMaxDynamicSharedMemorySize, GEMM_SMEM);
    cudaFuncSetAttribute(hmma_gemm<2>,
                         cudaFuncAttributeMaxDynamicSharedMemorySize, GEMM_SMEM);
    cudaFuncSetAttribute(hmma_gemm<3>,
                         cudaFuncAttributeMaxDynamicSharedMemorySize, GEMM_SMEM);

    // --- prep: pure converts, no transposes ---
    posbias_kernel<<<4096, 256>>>(pe, pb);
    conv_half<<<M_ROWS * E_DIM / 1024, 256>>>(x, xf);

    const int NB_1M = 1024 * 1024 / 1024;   // 1024 blocks for 1M elements
    conv_w<<<NB_1M, 256>>>(Wq, wq, 1024, 4096, 0);
    conv_w<<<NB_1M, 256>>>(Wk, wq, 1024, 4096, 1024);
    conv_w<<<NB_1M, 256>>>(Wv, wq, 1024, 4096, 2048);
    conv_w<<<NB_1M, 256>>>(Wg, wq, 1024, 4096, 3072);
    conv_w<<<NB_1M, 256>>>(Wo, wo, 1024, 1024, 0);
    conv_wff<<<4 * NB_1M, 256>>>(Wf1, Wfg, wff);
    conv_w<<<4 * NB_1M, 256>>>(Wf2, w2, 1024, 1024, 0);
    pack_bias<<<48, 256>>>(bq, bk, bv, bg, bf1, bfg, biasq, biasf);

    // --- QKV + gate projection (fp16 output) ---
    hmma_gemm<3><<<dim3(32, 32), 256, GEMM_SMEM>>>(xf, wq, biasq, nullptr,
                                                   qkvgf, nullptr,
                                                   M_ROWS, 4096, 1024);
    // --- fp16 flash attention ---
    attention_f16<<<dim3(8, 64), 256, ATT_SMEM>>>(qkvgf, pb, ctxf);
    // --- output projection ---
    hmma_gemm<0><<<dim3(8, 32), 256, GEMM_SMEM>>>(ctxf, wo, bo, tmp,
                                                  nullptr, nullptr,
                                                  M_ROWS, 1024, 1024);
    // --- gate + residual + LN1 ---
    ln1_kernel<<<M_ROWS, 256>>>(x, tmp, qkvgf, l1g, l1b, x1, x1f);
    // --- FFN up with fused SwiGLU epilogue ---
    hmma_gemm<1><<<dim3(64, 32), 256, GEMM_SMEM>>>(x1f, wff, biasf, nullptr,
                                                   h1f, nullptr,
                                                   M_ROWS, 8192, 1024);
    // --- FFN down + fused residual add (tmp = x1 + ff) ---
    hmma_gemm<2><<<dim3(8, 32), 256, GEMM_SMEM>>>(h1f, w2, bf2, tmp,
                                                  nullptr, x1,
                                                  M_ROWS, 1024, 4096);
    // --- LN2 ---
    ln2_kernel<<<M_ROWS, 256>>>(tmp, l2g, l2b, out);
}

// round 11
// speedup vs baseline: 1.0268x; 1.0268x over previous
#include <cuda_runtime.h>
#include <cuda_fp16.h>
#include <cstdint>
#include <cstddef>

// Problem constants
#define E_DIM 1024
#define S_LEN 1024
#define B_SZ 4
#define NH 16
#define HD 64
#define FF_DIM 4096
#define M_ROWS (B_SZ * S_LEN)   // 4096

// ---------------- scratch (static device globals; no allocation) ----------------
__device__ float g_tmp[M_ROWS * E_DIM];          // attn_out, later (x1+ff)
__device__ float g_x1[M_ROWS * E_DIM];
__device__ float g_pb[S_LEN * S_LEN];

// fp16 activations
__device__ __half g_qkvgf[M_ROWS * 4096];        // [q|k|v|gate] fp16
__device__ __half g_xf[M_ROWS * E_DIM];
__device__ __half g_ctxf[M_ROWS * E_DIM];
__device__ __half g_x1f[M_ROWS * E_DIM];
__device__ __half g_h1f[(size_t)M_ROWS * FF_DIM];

// fp16 weights in ORIGINAL [K,N] layout (B fed via ldmatrix.trans)
__device__ __half g_wqkvg[1024 * 4096];          // cols: [Wq|Wk|Wv|Wg]
__device__ __half g_wo[1024 * 1024];
__device__ __half g_wff[1024 * 8192];            // cols interleaved: 2n = Wf1_n, 2n+1 = Wfg_n
__device__ __half g_wf2[4096 * 1024];

__device__ float g_bias_qkvg[4096];
__device__ float g_bias_ff[8192];                 // interleaved bf1/bfg

#define L2E 1.4426950408889634f

// =================== PTX helpers (baseline sm_80+ features only) ===================
__device__ __forceinline__ uint32_t smem_u32(const void* p) {
    uint32_t a;
    asm("{ .reg .u64 t; cvta.to.shared.u64 t, %1; cvt.u32.u64 %0, t; }" : "=r"(a) : "l"(p));
    return a;
}
__device__ __forceinline__ void cp16(uint32_t dst, const void* src) {
    asm volatile("cp.async.cg.shared.global [%0], [%1], 16;" :: "r"(dst), "l"(src));
}
#define CP_COMMIT() asm volatile("cp.async.commit_group;" ::: "memory")
#define CP_WAIT1()  asm volatile("cp.async.wait_group 1;" ::: "memory")
#define CP_WAIT0()  asm volatile("cp.async.wait_group 0;" ::: "memory")

__device__ __forceinline__ void ldm_x4(uint32_t& r0, uint32_t& r1, uint32_t& r2,
                                       uint32_t& r3, uint32_t addr) {
    asm volatile("ldmatrix.sync.aligned.m8n8.x4.shared.b16 {%0,%1,%2,%3}, [%4];"
                 : "=r"(r0), "=r"(r1), "=r"(r2), "=r"(r3) : "r"(addr));
}
__device__ __forceinline__ void ldm_x4t(uint32_t& r0, uint32_t& r1, uint32_t& r2,
                                        uint32_t& r3, uint32_t addr) {
    asm volatile("ldmatrix.sync.aligned.m8n8.x4.trans.shared.b16 {%0,%1,%2,%3}, [%4];"
                 : "=r"(r0), "=r"(r1), "=r"(r2), "=r"(r3) : "r"(addr));
}
// fp16 MMA
__device__ __forceinline__ void mma16816h(float* c, const uint32_t* a,
                                          uint32_t b0, uint32_t b1) {
    asm volatile(
        "mma.sync.aligned.m16n8k16.row.col.f32.f16.f16.f32 "
        "{%0,%1,%2,%3}, {%4,%5,%6,%7}, {%8,%9}, {%0,%1,%2,%3};"
        : "+f"(c[0]), "+f"(c[1]), "+f"(c[2]), "+f"(c[3])
        : "r"(a[0]), "r"(a[1]), "r"(a[2]), "r"(a[3]), "r"(b0), "r"(b1));
}
__device__ __forceinline__ float ex2f(float x) {
    float y;
    asm("ex2.approx.ftz.f32 %0, %1;" : "=f"(y) : "f"(x));
    return y;
}

// =================== HMMA GEMM (fp16, B via trans-ldmatrix from [K,N]) ===================
// A: [M,K] fp16. W: [K,N] fp16 (original layout).
// MODE 0: C[M,N] fp32 = A@W + bias
// MODE 1: SwiGLU: Of[M,N/2] fp16 = (c_even+b_even) * sigmoid(c_odd+b_odd)
// MODE 2: C = A@W + bias + R
// MODE 3: Of[M,N] fp16 = A@W + bias
// smem stage: A[128r x 80B] @0 (10240B), B[32k x 272B] @10240 (8704B); 3 stages.
#define B_SOFF 10240
#define STAGE_BYTES 18944
#define GEMM_SMEM (3 * STAGE_BYTES)

template <int MODE>
__global__ __launch_bounds__(256, 2)
void hmma_gemm(const __half* __restrict__ Af, const __half* __restrict__ W,
               const float* __restrict__ bias, float* __restrict__ C,
               __half* __restrict__ Of, const float* __restrict__ R,
               int M, int N, int K) {
    extern __shared__ char smem[];
    const uint32_t sb = smem_u32(smem);
    const int tid = threadIdx.x;
    const int wid = tid >> 5, lane = tid & 31;
    const int brow = blockIdx.y * 128, bcol = blockIdx.x * 128;
    const int wm = (wid >> 2) * 64, wn = (wid & 3) * 32;
    const int nst = K >> 5;

    const int ar0 = tid >> 2, ar1 = (tid + 256) >> 2;
    const int ac0 = tid & 3,  ac1 = (tid + 256) & 3;
    const uint32_t aso0 = (uint32_t)(ar0 * 80 + ac0 * 16);
    const uint32_t aso1 = (uint32_t)(ar1 * 80 + ac1 * 16);
    const int br0 = tid >> 4, br1 = (tid + 256) >> 4;
    const int bc0 = tid & 15, bc1 = (tid + 256) & 15;
    const uint32_t bso0 = (uint32_t)(B_SOFF + br0 * 272 + bc0 * 16);
    const uint32_t bso1 = (uint32_t)(B_SOFF + br1 * 272 + bc1 * 16);

#define LOAD_STAGE(s, buf) do {                                               \
        const uint32_t stb_ = sb + (buf) * STAGE_BYTES;                       \
        cp16(stb_ + aso0, Af + (size_t)(brow + ar0) * K + (s) * 32 + ac0 * 8);\
        cp16(stb_ + aso1, Af + (size_t)(brow + ar1) * K + (s) * 32 + ac1 * 8);\
        cp16(stb_ + bso0, W + (size_t)((s) * 32 + br0) * N + bcol + bc0 * 8); \
        cp16(stb_ + bso1, W + (size_t)((s) * 32 + br1) * N + bcol + bc1 * 8); \
    } while (0)

    float acc[4][4][4];
#pragma unroll
    for (int i = 0; i < 4; i++)
#pragma unroll
        for (int j = 0; j < 4; j++)
#pragma unroll
            for (int r = 0; r < 4; r++) acc[i][j][r] = 0.f;

    LOAD_STAGE(0, 0); CP_COMMIT();
    LOAD_STAGE(1, 1); CP_COMMIT();

    const uint32_t a_lrow = (uint32_t)(lane & 15);
    const uint32_t a_koff = (uint32_t)((lane & 16) >> 1);
    const uint32_t b_krow = (uint32_t)((lane & 7) + (lane & 8));
    const uint32_t b_noff2 = (uint32_t)((lane & 16) >> 1) * 2;

    for (int s = 0; s < nst; s++) {
        CP_WAIT1();
        __syncthreads();
        if (s + 2 < nst) LOAD_STAGE(s + 2, (s + 2) % 3);
        CP_COMMIT();
        const uint32_t stb = sb + (uint32_t)(s % 3) * STAGE_BYTES;

#pragma unroll
        for (int kk = 0; kk < 32; kk += 16) {
            uint32_t bf[2][4];
#pragma unroll
            for (int ni = 0; ni < 2; ni++) {
                const uint32_t addr = stb + B_SOFF +
                    (uint32_t)(kk + b_krow) * 272 + (uint32_t)(wn + ni * 16) * 2 + b_noff2;
                ldm_x4t(bf[ni][0], bf[ni][1], bf[ni][2], bf[ni][3], addr);
            }
            const uint32_t akcol = (uint32_t)kk + a_koff;
#pragma unroll
            for (int mi = 0; mi < 4; mi++) {
                uint32_t a[4];
                const uint32_t addr = stb + (uint32_t)(wm + mi * 16 + a_lrow) * 80 + akcol * 2;
                ldm_x4(a[0], a[1], a[2], a[3], addr);
#pragma unroll
                for (int nj = 0; nj < 4; nj++) {
                    const int g = nj >> 1, p = (nj & 1) * 2;
                    mma16816h(acc[mi][nj], a, bf[g][p], bf[g][p + 1]);
                }
            }
        }
    }

    const int qr = lane >> 2, qc = (lane & 3) * 2;
#pragma unroll
    for (int mi = 0; mi < 4; mi++) {
        const size_t gr = (size_t)(brow + wm + mi * 16 + qr);
#pragma unroll
        for (int nj = 0; nj < 4; nj++) {
            const int gc = bcol + wn + nj * 8 + qc;
            const float2 b2 = *(const float2*)(bias + gc);
            if (MODE == 0 || MODE == 2) {
                float2 o0, o1;
                o0.x = acc[mi][nj][0] + b2.x;
                o0.y = acc[mi][nj][1] + b2.y;
                o1.x = acc[mi][nj][2] + b2.x;
                o1.y = acc[mi][nj][3] + b2.y;
                if (MODE == 2) {
                    const float2 r0 = *(const float2*)(R + gr * N + gc);
                    const float2 r1 = *(const float2*)(R + (gr + 8) * N + gc);
                    o0.x += r0.x; o0.y += r0.y;
                    o1.x += r1.x; o1.y += r1.y;
                }
                *(float2*)(C + gr * N + gc)       = o0;
                *(float2*)(C + (gr + 8) * N + gc) = o1;
            } else if (MODE == 3) {
                const __half2 o0 = __floats2half2_rn(acc[mi][nj][0] + b2.x,
                                                     acc[mi][nj][1] + b2.y);
                const __half2 o1 = __floats2half2_rn(acc[mi][nj][2] + b2.x,
                                                     acc[mi][nj][3] + b2.y);
                *(__half2*)(Of + gr * N + gc)       = o0;
                *(__half2*)(Of + (gr + 8) * N + gc) = o1;
            } else {
                const float h1v0 = acc[mi][nj][0] + b2.x;
                const float hg0  = acc[mi][nj][1] + b2.y;
                const float h1v1 = acc[mi][nj][2] + b2.x;
                const float hg1  = acc[mi][nj][3] + b2.y;
                const float o0 = h1v0 / (1.f + ex2f(-hg0 * L2E));
                const float o1 = h1v1 / (1.f + ex2f(-hg1 * L2E));
                const size_t co = (size_t)(gc >> 1);
                Of[gr * (N >> 1) + co]       = __float2half(o0);
                Of[(gr + 8) * (N >> 1) + co] = __float2half(o1);
            }
        }
    }
#undef LOAD_STAGE
}

// =================== fp16 flash attention ===================
#define ATT_Q 0
#define ATT_KV0 18432
#define ATT_KV1 36864
#define ATT_SMEM 55296

__global__ __launch_bounds__(256, 2)
void attention_f16(const __half* __restrict__ QKVF, const float* __restrict__ PB,
                   __half* __restrict__ CTXF) {
    extern __shared__ char smem[];
    const uint32_t sbase = smem_u32(smem);
    const int tid = threadIdx.x;
    const int wid = tid >> 5, lane = tid & 31;
    const int b = blockIdx.y >> 4, h = blockIdx.y & 15;
    const int q0 = blockIdx.x * 128;
    const int wr = wid * 16;

#pragma unroll
    for (int it = 0; it < 4; it++) {
        const int c = tid + it * 256;
        const int r = c >> 3, co = c & 7;
        cp16(sbase + ATT_Q + (uint32_t)(r * 144 + co * 16),
             QKVF + (((size_t)b << 10) + q0 + r) * 4096 + h * 64 + co * 8);
    }
#define LOAD_KV(kt, bufoff) do {                                              \
        _Pragma("unroll")                                                     \
        for (int it = 0; it < 4; it++) {                                      \
            const int c = tid + it * 256;                                     \
            const int kv = c >> 9;                                            \
            const int cc = c & 511;                                           \
            const int r = cc >> 3, co = cc & 7;                               \
            cp16(sbase + (bufoff) + (uint32_t)(kv * 9216 + r * 144 + co * 16),\
                 QKVF + (((size_t)b << 10) + (kt) * 64 + r) * 4096 +          \
                     (1 + kv) * 1024 + h * 64 + co * 8);                      \
        }                                                                     \
    } while (0)

    LOAD_KV(0, ATT_KV0);
    CP_COMMIT();

    const uint32_t a_lrow = (uint32_t)(lane & 15);
    const uint32_t a_koff2 = (uint32_t)((lane & 16) >> 1) * 2;
    const uint32_t b_lrow = (uint32_t)((lane & 7) + ((lane & 16) >> 1));
    const uint32_t b_koff2 = (uint32_t)(lane & 8) * 2;
    const uint32_t v_row = (uint32_t)((lane & 7) + (lane & 8));
    const uint32_t v_col2 = (uint32_t)((lane & 16) >> 1) * 2;

    const int qr = lane >> 2, qc = (lane & 3) * 2;
    float m0 = -1e30f, m1 = -1e30f, l0 = 0.f, l1 = 0.f;
    float oacc[8][4];
#pragma unroll
    for (int nt = 0; nt < 8; nt++)
#pragma unroll
        for (int e = 0; e < 4; e++) oacc[nt][e] = 0.f;

    for (int kt = 0; kt < 16; kt++) {
        CP_WAIT0();
        __syncthreads();
        const uint32_t kvb = (kt & 1) ? ATT_KV1 : ATT_KV0;
        if (kt < 15) LOAD_KV(kt + 1, (kt & 1) ? ATT_KV0 : ATT_KV1);
        CP_COMMIT();

        float sa[8][4];
#pragma unroll
        for (int nt = 0; nt < 8; nt++)
#pragma unroll
            for (int e = 0; e < 4; e++) sa[nt][e] = 0.f;

#pragma unroll
        for (int k16 = 0; k16 < 4; k16++) {
            uint32_t q[4];
            const uint32_t qaddr =
                sbase + ATT_Q + (uint32_t)(wr + a_lrow) * 144 + k16 * 32 + a_koff2;
            ldm_x4(q[0], q[1], q[2], q[3], qaddr);
#pragma unroll
            for (int ntp = 0; ntp < 4; ntp++) {
                uint32_t kf[4];
                const uint32_t kaddr =
                    sbase + kvb + (uint32_t)(ntp * 16 + b_lrow) * 144 + k16 * 32 + b_koff2;
                ldm_x4(kf[0], kf[1], kf[2], kf[3], kaddr);
                mma16816h(sa[2 * ntp],     q, kf[0], kf[1]);
                mma16816h(sa[2 * ntp + 1], q, kf[2], kf[3]);
            }
        }

        const size_t r0g = (size_t)(q0 + wr + qr);
        const size_t pb0 = r0g * 1024 + kt * 64 + qc;
        const size_t pb1 = (r0g + 8) * 1024 + kt * 64 + qc;
#pragma unroll
        for (int nt = 0; nt < 8; nt++) {
            const float2 p0 = *(const float2*)&PB[pb0 + nt * 8];
            const float2 p1 = *(const float2*)&PB[pb1 + nt * 8];
            sa[nt][0] = sa[nt][0] * 0.125f + p0.x;
            sa[nt][1] = sa[nt][1] * 0.125f + p0.y;
            sa[nt][2] = sa[nt][2] * 0.125f + p1.x;
            sa[nt][3] = sa[nt][3] * 0.125f + p1.y;
        }

        float tm0 = -1e30f, tm1 = -1e30f;
#pragma unroll
        for (int nt = 0; nt < 8; nt++) {
            tm0 = fmaxf(tm0, fmaxf(sa[nt][0], sa[nt][1]));
            tm1 = fmaxf(tm1, fmaxf(sa[nt][2], sa[nt][3]));
        }
        tm0 = fmaxf(tm0, __shfl_xor_sync(0xffffffffu, tm0, 1));
        tm0 = fmaxf(tm0, __shfl_xor_sync(0xffffffffu, tm0, 2));
        tm1 = fmaxf(tm1, __shfl_xor_sync(0xffffffffu, tm1, 1));
        tm1 = fmaxf(tm1, __shfl_xor_sync(0xffffffffu, tm1, 2));
        const float mn0 = fmaxf(m0, tm0), mn1 = fmaxf(m1, tm1);
        const float cr0 = ex2f((m0 - mn0) * L2E), cr1 = ex2f((m1 - mn1) * L2E);
        m0 = mn0; m1 = mn1;

        float rs0 = 0.f, rs1 = 0.f;
#pragma unroll
        for (int nt = 0; nt < 8; nt++) {
            sa[nt][0] = ex2f((sa[nt][0] - mn0) * L2E);
            sa[nt][1] = ex2f((sa[nt][1] - mn0) * L2E);
            sa[nt][2] = ex2f((sa[nt][2] - mn1) * L2E);
            sa[nt][3] = ex2f((sa[nt][3] - mn1) * L2E);
            rs0 += sa[nt][0] + sa[nt][1];
            rs1 += sa[nt][2] + sa[nt][3];
        }
        rs0 += __shfl_xor_sync(0xffffffffu, rs0, 1);
        rs0 += __shfl_xor_sync(0xffffffffu, rs0, 2);
        rs1 += __shfl_xor_sync(0xffffffffu, rs1, 1);
        rs1 += __shfl_xor_sync(0xffffffffu, rs1, 2);
        l0 = l0 * cr0 + rs0;
        l1 = l1 * cr1 + rs1;
#pragma unroll
        for (int nt = 0; nt < 8; nt++) {
            oacc[nt][0] *= cr0; oacc[nt][1] *= cr0;
            oacc[nt][2] *= cr1; oacc[nt][3] *= cr1;
        }

#pragma unroll
        for (int j = 0; j < 4; j++) {
            uint32_t pha[4];
            {
                const float* s0 = sa[2 * j];
                const float* s1 = sa[2 * j + 1];
                const __half2 a0 = __floats2half2_rn(s0[0], s0[1]);
                const __half2 a1 = __floats2half2_rn(s0[2], s0[3]);
                const __half2 a2 = __floats2half2_rn(s1[0], s1[1]);
                const __half2 a3 = __floats2half2_rn(s1[2], s1[3]);
                pha[0] = *(const uint32_t*)&a0;
                pha[1] = *(const uint32_t*)&a1;
                pha[2] = *(const uint32_t*)&a2;
                pha[3] = *(const uint32_t*)&a3;
            }
#pragma unroll
            for (int ntp = 0; ntp < 4; ntp++) {
                uint32_t vf[4];
                const uint32_t vaddr = sbase + kvb + 9216 +
                    (uint32_t)(j * 16 + v_row) * 144 + (uint32_t)(ntp * 16) * 2 + v_col2;
                ldm_x4t(vf[0], vf[1], vf[2], vf[3], vaddr);
                mma16816h(oacc[2 * ntp],     pha, vf[0], vf[1]);
                mma16816h(oacc[2 * ntp + 1], pha, vf[2], vf[3]);
            }
        }
        __syncthreads();
    }

    const float inv0 = 1.f / l0, inv1 = 1.f / l1;
    const size_t cr0 = (size_t)((b << 10) + q0 + wr + qr);
    const size_t colb = (size_t)(h * 64 + qc);
#pragma unroll
    for (int nt = 0; nt < 8; nt++) {
        const __half2 h2a = __floats2half2_rn(oacc[nt][0] * inv0, oacc[nt][1] * inv0);
        const __half2 h2b = __floats2half2_rn(oacc[nt][2] * inv1, oacc[nt][3] * inv1);
        *(__half2*)(CTXF + cr0 * 1024 + colb + nt * 8)       = h2a;
        *(__half2*)(CTXF + (cr0 + 8) * 1024 + colb + nt * 8) = h2b;
    }
#undef LOAD_KV
}

// =================== merged prep: ONE launch does everything ===================
// block ranges (each block handles 1024 fp32 elements = 256 threads x float4):
// [0,4096)       posbias (1M outputs, 8 floats read each)
// [4096,8192)    x -> fp16           (4M elements)
// [8192,12288)   Wq/Wk/Wv/Wg -> wqkvg col-packed (4 x 1M)
// [12288,13312)  Wo                  (1M)
// [13312,17408)  Wf1+Wfg interleave  (4M each)
// [17408,21504)  Wf2                 (4M)
// [21504,21552)  bias packing        (12288 scalars)
#define PREP_BLOCKS 21552

__device__ __forceinline__ uint2 f4_to_h4(float4 v) {
    const __half2 a = __floats2half2_rn(v.x, v.y);
    const __half2 b = __floats2half2_rn(v.z, v.w);
    uint2 o;
    o.x = *(const uint32_t*)&a;
    o.y = *(const uint32_t*)&b;
    return o;
}

__global__ __launch_bounds__(256)
void prep_all(const float* __restrict__ pe, float* __restrict__ pb,
              const float* __restrict__ x, __half* __restrict__ xf,
              const float* __restrict__ Wq, const float* __restrict__ Wk,
              const float* __restrict__ Wv, const float* __restrict__ Wg,
              const float* __restrict__ Wo_, const float* __restrict__ Wf1,
              const float* __restrict__ Wfg, const float* __restrict__ Wf2,
              __half* __restrict__ wq, __half* __restrict__ wo,
              __half* __restrict__ wff, __half* __restrict__ w2,
              const float* __restrict__ bq, const float* __restrict__ bk,
              const float* __restrict__ bv, const float* __restrict__ bg,
              const float* __restrict__ bf1, const float* __restrict__ bfg,
              float* __restrict__ biasq, float* __restrict__ biasf) {
    const int blk = blockIdx.x;
    const int t = threadIdx.x;

    if (blk < 4096) {                      // pos bias mean
        const size_t i = (size_t)blk * 256 + t;
        const float4 a = *(const float4*)&pe[i * 8];
        const float4 b = *(const float4*)&pe[i * 8 + 4];
        pb[i] = (a.x + a.y + a.z + a.w + b.x + b.y + b.z + b.w) * 0.125f;
    } else if (blk < 8192) {               // x -> fp16 (4M elements)
        const size_t i = ((size_t)(blk - 4096) * 256 + t) * 4;
        *(uint2*)(xf + i) = f4_to_h4(*(const float4*)(x + i));
    } else if (blk < 12288) {              // QKVG weights, col-packed into [1024,4096]
        const int w = (blk - 8192) >> 10;
        const float* W = (w == 0) ? Wq : (w == 1) ? Wk : (w == 2) ? Wv : Wg;
        const size_t i = ((size_t)((blk - 8192) & 1023) * 256 + t) * 4;
        const size_t r = i >> 10;
        const int c = (int)(i & 1023);
        *(uint2*)(wq + r * 4096 + w * 1024 + c) = f4_to_h4(*(const float4*)(W + i));
    } else if (blk < 13312) {              // Wo (1M)
        const size_t i = ((size_t)(blk - 12288) * 256 + t) * 4;
        *(uint2*)(wo + i) = f4_to_h4(*(const float4*)(Wo_ + i));
    } else if (blk < 17408) {              // Wf1/Wfg interleave (4M each)
        const size_t i = ((size_t)(blk - 13312) * 256 + t) * 4;
        const float4 a = *(const float4*)(Wf1 + i);
        const float4 g = *(const float4*)(Wfg + i);
        uint4 o;
        const __half2 p0 = __floats2half2_rn(a.x, g.x);
        const __half2 p1 = __floats2half2_rn(a.y, g.y);
        const __half2 p2 = __floats2half2_rn(a.z, g.z);
        const __half2 p3 = __floats2half2_rn(a.w, g.w);
        o.x = *(const uint32_t*)&p0;
        o.y = *(const uint32_t*)&p1;
        o.z = *(const uint32_t*)&p2;
        o.w = *(const uint32_t*)&p3;
        *(uint4*)(wff + i * 2) = o;
    } else if (blk < 21504) {              // Wf2 (4M)
        const size_t i = ((size_t)(blk - 17408) * 256 + t) * 4;
        *(uint2*)(w2 + i) = f4_to_h4(*(const float4*)(Wf2 + i));
    } else {                               // bias packing
        const int i = (blk - 21504) * 256 + t;   // 0..12287
        if (i < 1024) biasq[i] = bq[i];
        else if (i < 2048) biasq[i] = bk[i - 1024];
        else if (i < 3072) biasq[i] = bv[i - 2048];
        else if (i < 4096) biasq[i] = bg[i - 3072];
        else if (i < 8192) biasf[2 * (i - 4096)] = bf1[i - 4096];
        else biasf[2 * (i - 8192) + 1] = bfg[i - 8192];
    }
}

// ---------------- LN1 ----------------
__global__ __launch_bounds__(256)
void ln1_kernel(const float* __restrict__ x, const float* __restrict__ attn,
                const __half* __restrict__ qkvgf, const float* __restrict__ gw,
                const float* __restrict__ gb, float* __restrict__ x1,
                __half* __restrict__ x1f) {
    const size_t base = (size_t)blockIdx.x * E_DIM;
    const size_t gbase = (size_t)blockIdx.x * 4096 + 3072;
    const int t = threadIdx.x;
    float vals[4];
    float s = 0.f, s2 = 0.f;
#pragma unroll
    for (int i = 0; i < 4; i++) {
        const int c = t + i * 256;
        const float gp = __half2float(qkvgf[gbase + c]);
        const float sg = 1.f / (1.f + __expf(-gp));
        const float val = x[base + c] + attn[base + c] * sg;
        vals[i] = val; s += val; s2 += val * val;
    }
    __shared__ float rsm[8], rs2[8];
#pragma unroll
    for (int o = 16; o; o >>= 1) {
        s  += __shfl_xor_sync(0xffffffffu, s,  o);
        s2 += __shfl_xor_sync(0xffffffffu, s2, o);
    }
    if ((t & 31) == 0) { rsm[t >> 5] = s; rs2[t >> 5] = s2; }
    __syncthreads();
    float S = 0.f, S2 = 0.f;
#pragma unroll
    for (int i = 0; i < 8; i++) { S += rsm[i]; S2 += rs2[i]; }
    const float mean = S * (1.f / E_DIM);
    const float var = S2 * (1.f / E_DIM) - mean * mean;
    const float inv = rsqrtf(var + 1e-6f);
#pragma unroll
    for (int i = 0; i < 4; i++) {
        const int c = t + i * 256;
        const float v = (vals[i] - mean) * inv * gw[c] + gb[c];
        x1[base + c] = v;
        x1f[base + c] = __float2half(v);
    }
}

// ---------------- LN2 (input already contains x1+ff residual) ----------------
__global__ __launch_bounds__(256)
void ln2_kernel(const float* __restrict__ ff,
                const float* __restrict__ gw, const float* __restrict__ gb,
                float* __restrict__ out) {
    const size_t base = (size_t)blockIdx.x * E_DIM;
    const int t = threadIdx.x;
    float vals[4];
    float s = 0.f, s2 = 0.f;
#pragma unroll
    for (int i = 0; i < 4; i++) {
        const int c = t + i * 256;
        const float val = ff[base + c];
        vals[i] = val; s += val; s2 += val * val;
    }
    __shared__ float rsm[8], rs2[8];
#pragma unroll
    for (int o = 16; o; o >>= 1) {
        s  += __shfl_xor_sync(0xffffffffu, s,  o);
        s2 += __shfl_xor_sync(0xffffffffu, s2, o);
    }
    if ((t & 31) == 0) { rsm[t >> 5] = s; rs2[t >> 5] = s2; }
    __syncthreads();
    float S = 0.f, S2 = 0.f;
#pragma unroll
    for (int i = 0; i < 8; i++) { S += rsm[i]; S2 += rs2[i]; }
    const float mean = S * (1.f / E_DIM);
    const float var = S2 * (1.f / E_DIM) - mean * mean;
    const float inv = rsqrtf(var + 1e-6f);
#pragma unroll
    for (int i = 0; i < 4; i++) {
        const int c = t + i * 256;
        out[base + c] = (vals[i] - mean) * inv * gw[c] + gb[c];
    }
}

// =================== launch ===================
extern "C" void kernel_launch(void* const* d_in, const int* in_sizes, int n_in,
                              void* d_out, int out_size) {
    const float* x   = (const float*)d_in[0];
    const float* pe  = (const float*)d_in[1];
    const float* Wq  = (const float*)d_in[2];
    const float* bq  = (const float*)d_in[3];
    const float* Wk  = (const float*)d_in[4];
    const float* bk  = (const float*)d_in[5];
    const float* Wv  = (const float*)d_in[6];
    const float* bv  = (const float*)d_in[7];
    const float* Wo  = (const float*)d_in[8];
    const float* bo  = (const float*)d_in[9];
    const float* Wg  = (const float*)d_in[10];
    const float* bg  = (const float*)d_in[11];
    const float* Wf1 = (const float*)d_in[12];
    const float* bf1 = (const float*)d_in[13];
    const float* Wfg = (const float*)d_in[14];
    const float* bfg = (const float*)d_in[15];
    const float* Wf2 = (const float*)d_in[16];
    const float* bf2 = (const float*)d_in[17];
    const float* l1g = (const float*)d_in[18];
    const float* l1b = (const float*)d_in[19];
    const float* l2g = (const float*)d_in[20];
    const float* l2b = (const float*)d_in[21];
    float* out = (float*)d_out;

    float *tmp, *x1, *pb, *biasq, *biasf;
    __half *qkvgf, *xf, *ctxf, *x1f, *h1f;
    __half *wq, *wo, *wff, *w2;
    cudaGetSymbolAddress((void**)&tmp, g_tmp);
    cudaGetSymbolAddress((void**)&x1, g_x1);
    cudaGetSymbolAddress((void**)&pb, g_pb);
    cudaGetSymbolAddress((void**)&biasq, g_bias_qkvg);
    cudaGetSymbolAddress((void**)&biasf, g_bias_ff);
    cudaGetSymbolAddress((void**)&qkvgf, g_qkvgf);
    cudaGetSymbolAddress((void**)&xf, g_xf);
    cudaGetSymbolAddress((void**)&ctxf, g_ctxf);
    cudaGetSymbolAddress((void**)&x1f, g_x1f);
    cudaGetSymbolAddress((void**)&h1f, g_h1f);
    cudaGetSymbolAddress((void**)&wq, g_wqkvg);
    cudaGetSymbolAddress((void**)&wo, g_wo);
    cudaGetSymbolAddress((void**)&wff, g_wff);
    cudaGetSymbolAddress((void**)&w2, g_wf2);

    cudaFuncSetAttribute(attention_f16,
                         cudaFuncAttributeMaxDynamicSharedMemorySize, ATT_SMEM);
    cudaFuncSetAttribute(hmma_gemm<0>,
                         cudaFuncAttributeMaxDynamicSharedMemorySize, GEMM_SMEM);
    cudaFuncSetAttribute(hmma_gemm<1>,
                         cudaFuncAttributeMaxDynamicSharedMemorySize, GEMM_SMEM);
    cudaFuncSetAttribute(hmma_gemm<2>,
                         cudaFuncAttributeMaxDynamicSharedMemorySize, GEMM_SMEM);
    cudaFuncSetAttribute(hmma_gemm<3>,
                         cudaFuncAttributeMaxDynamicSharedMemorySize, GEMM_SMEM);

    // --- single merged prep launch ---
    prep_all<<<PREP_BLOCKS, 256>>>(pe, pb, x, xf,
                                   Wq, Wk, Wv, Wg, Wo, Wf1, Wfg, Wf2,
                                   wq, wo, wff, w2,
                                   bq, bk, bv, bg, bf1, bfg, biasq, biasf);

    // --- QKV + gate projection (fp16 output) ---
    hmma_gemm<3><<<dim3(32, 32), 256, GEMM_SMEM>>>(xf, wq, biasq, nullptr,
                                                   qkvgf, nullptr,
                                                   M_ROWS, 4096, 1024);
    // --- fp16 flash attention ---
    attention_f16<<<dim3(8, 64), 256, ATT_SMEM>>>(qkvgf, pb, ctxf);
    // --- output projection ---
    hmma_gemm<0><<<dim3(8, 32), 256, GEMM_SMEM>>>(ctxf, wo, bo, tmp,
                                                  nullptr, nullptr,
                                                  M_ROWS, 1024, 1024);
    // --- gate + residual + LN1 ---
    ln1_kernel<<<M_ROWS, 256>>>(x, tmp, qkvgf, l1g, l1b, x1, x1f);
    // --- FFN up with fused SwiGLU epilogue ---
    hmma_gemm<1><<<dim3(64, 32), 256, GEMM_SMEM>>>(x1f, wff, biasf, nullptr,
                                                   h1f, nullptr,
                                                   M_ROWS, 8192, 1024);
    // --- FFN down + fused residual add (tmp = x1 + ff) ---
    hmma_gemm<2><<<dim3(8, 32), 256, GEMM_SMEM>>>(h1f, w2, bf2, tmp,
                                                  nullptr, x1,
                                                  M_ROWS, 1024, 4096);
    // --- LN2 ---
    ln2_kernel<<<M_ROWS, 256>>>(tmp, l2g, l2b, out);
}

// round 12
// speedup vs baseline: 1.0571x; 1.0295x over previous
#include <cuda_runtime.h>
#include <cuda_fp16.h>
#include <cstdint>
#include <cstddef>

// Problem constants
#define E_DIM 1024
#define S_LEN 1024
#define B_SZ 4
#define NH 16
#define HD 64
#define FF_DIM 4096
#define M_ROWS (B_SZ * S_LEN)   // 4096

// ---------------- scratch (static device globals; no allocation) ----------------
__device__ float g_tmp[M_ROWS * E_DIM];          // attn_out, later (x1+ff)
__device__ float g_x1[M_ROWS * E_DIM];
__device__ float g_pb[S_LEN * S_LEN];

// fp16 activations
__device__ __half g_qkvgf[M_ROWS * 4096];        // [q|k|v|gate] fp16
__device__ __half g_xf[M_ROWS * E_DIM];
__device__ __half g_ctxf[M_ROWS * E_DIM];
__device__ __half g_x1f[M_ROWS * E_DIM];
__device__ __half g_h1f[(size_t)M_ROWS * FF_DIM];

// fp16 weights in ORIGINAL [K,N] layout (B fed via ldmatrix.trans)
__device__ __half g_wqkvg[1024 * 4096];          // cols: [Wq|Wk|Wv|Wg]
__device__ __half g_wo[1024 * 1024];
__device__ __half g_wff[1024 * 8192];            // cols interleaved: 2n = Wf1_n, 2n+1 = Wfg_n
__device__ __half g_wf2[4096 * 1024];

__device__ float g_bias_qkvg[4096];
__device__ float g_bias_ff[8192];                 // interleaved bf1/bfg

#define L2E 1.4426950408889634f

// =================== PTX helpers (baseline sm_80+ features only) ===================
__device__ __forceinline__ uint32_t smem_u32(const void* p) {
    uint32_t a;
    asm("{ .reg .u64 t; cvta.to.shared.u64 t, %1; cvt.u32.u64 %0, t; }" : "=r"(a) : "l"(p));
    return a;
}
__device__ __forceinline__ void cp16(uint32_t dst, const void* src) {
    asm volatile("cp.async.cg.shared.global [%0], [%1], 16;" :: "r"(dst), "l"(src));
}
#define CP_COMMIT() asm volatile("cp.async.commit_group;" ::: "memory")
#define CP_WAIT1()  asm volatile("cp.async.wait_group 1;" ::: "memory")
#define CP_WAIT0()  asm volatile("cp.async.wait_group 0;" ::: "memory")

__device__ __forceinline__ void ldm_x4(uint32_t& r0, uint32_t& r1, uint32_t& r2,
                                       uint32_t& r3, uint32_t addr) {
    asm volatile("ldmatrix.sync.aligned.m8n8.x4.shared.b16 {%0,%1,%2,%3}, [%4];"
                 : "=r"(r0), "=r"(r1), "=r"(r2), "=r"(r3) : "r"(addr));
}
__device__ __forceinline__ void ldm_x4t(uint32_t& r0, uint32_t& r1, uint32_t& r2,
                                        uint32_t& r3, uint32_t addr) {
    asm volatile("ldmatrix.sync.aligned.m8n8.x4.trans.shared.b16 {%0,%1,%2,%3}, [%4];"
                 : "=r"(r0), "=r"(r1), "=r"(r2), "=r"(r3) : "r"(addr));
}
// fp16 MMA
__device__ __forceinline__ void mma16816h(float* c, const uint32_t* a,
                                          uint32_t b0, uint32_t b1) {
    asm volatile(
        "mma.sync.aligned.m16n8k16.row.col.f32.f16.f16.f32 "
        "{%0,%1,%2,%3}, {%4,%5,%6,%7}, {%8,%9}, {%0,%1,%2,%3};"
        : "+f"(c[0]), "+f"(c[1]), "+f"(c[2]), "+f"(c[3])
        : "r"(a[0]), "r"(a[1]), "r"(a[2]), "r"(a[3]), "r"(b0), "r"(b1));
}
__device__ __forceinline__ float ex2f(float x) {
    float y;
    asm("ex2.approx.ftz.f32 %0, %1;" : "=f"(y) : "f"(x));
    return y;
}

// =================== HMMA GEMM (fp16, BK=64 stages, B via trans-ldmatrix) ===================
// A: [M,K] fp16. W: [K,N] fp16 (original layout).
// MODE 0: C[M,N] fp32 = A@W + bias
// MODE 1: SwiGLU: Of[M,N/2] fp16 = (c_even+b_even) * sigmoid(c_odd+b_odd)
// MODE 2: C = A@W + bias + R
// MODE 3: Of[M,N] fp16 = A@W + bias
// smem stage: A[128r x 144B] @0 (18432B), B[64k x 272B] @18432 (17408B); 3 stages.
#define B_SOFF 18432
#define STAGE_BYTES 35840
#define GEMM_SMEM (3 * STAGE_BYTES)

template <int MODE>
__global__ __launch_bounds__(256, 2)
void hmma_gemm(const __half* __restrict__ Af, const __half* __restrict__ W,
               const float* __restrict__ bias, float* __restrict__ C,
               __half* __restrict__ Of, const float* __restrict__ R,
               int M, int N, int K) {
    extern __shared__ char smem[];
    const uint32_t sb = smem_u32(smem);
    const int tid = threadIdx.x;
    const int wid = tid >> 5, lane = tid & 31;
    const int brow = blockIdx.y * 128, bcol = blockIdx.x * 128;
    const int wm = (wid >> 2) * 64, wn = (wid & 3) * 32;
    const int nst = K >> 6;    // BK=64

    // A: 1024 chunks (128 rows x 8 col16); B: 1024 chunks (64 rows x 16 col16)
    // thread handles A chunks tid, tid+256, ... and same for B (4 each)
#define LOAD_STAGE(s, buf) do {                                                 \
        const uint32_t stb_ = sb + (buf) * STAGE_BYTES;                         \
        _Pragma("unroll")                                                       \
        for (int it_ = 0; it_ < 4; it_++) {                                     \
            const int ca_ = tid + it_ * 256;                                    \
            const int ra_ = ca_ >> 3, cca_ = ca_ & 7;                           \
            cp16(stb_ + (uint32_t)(ra_ * 144 + cca_ * 16),                      \
                 Af + (size_t)(brow + ra_) * K + (s) * 64 + cca_ * 8);          \
            const int rb_ = ca_ >> 4, ccb_ = ca_ & 15;                          \
            cp16(stb_ + (uint32_t)(B_SOFF + rb_ * 272 + ccb_ * 16),             \
                 W + (size_t)((s) * 64 + rb_) * N + bcol + ccb_ * 8);           \
        }                                                                       \
    } while (0)

    float acc[4][4][4];
#pragma unroll
    for (int i = 0; i < 4; i++)
#pragma unroll
        for (int j = 0; j < 4; j++)
#pragma unroll
            for (int r = 0; r < 4; r++) acc[i][j][r] = 0.f;

    LOAD_STAGE(0, 0); CP_COMMIT();
    LOAD_STAGE(1, 1); CP_COMMIT();

    const uint32_t a_lrow = (uint32_t)(lane & 15);
    const uint32_t a_koff = (uint32_t)((lane & 16) >> 1);
    const uint32_t b_krow = (uint32_t)((lane & 7) + (lane & 8));
    const uint32_t b_noff2 = (uint32_t)((lane & 16) >> 1) * 2;

    for (int s = 0; s < nst; s++) {
        CP_WAIT1();
        __syncthreads();
        if (s + 2 < nst) LOAD_STAGE(s + 2, (s + 2) % 3);
        CP_COMMIT();
        const uint32_t stb = sb + (uint32_t)(s % 3) * STAGE_BYTES;

#pragma unroll
        for (int kk = 0; kk < 64; kk += 16) {
            uint32_t bf[2][4];
#pragma unroll
            for (int ni = 0; ni < 2; ni++) {
                const uint32_t addr = stb + B_SOFF +
                    (uint32_t)(kk + b_krow) * 272 + (uint32_t)(wn + ni * 16) * 2 + b_noff2;
                ldm_x4t(bf[ni][0], bf[ni][1], bf[ni][2], bf[ni][3], addr);
            }
            const uint32_t akcol = (uint32_t)kk + a_koff;
#pragma unroll
            for (int mi = 0; mi < 4; mi++) {
                uint32_t a[4];
                const uint32_t addr = stb + (uint32_t)(wm + mi * 16 + a_lrow) * 144 + akcol * 2;
                ldm_x4(a[0], a[1], a[2], a[3], addr);
#pragma unroll
                for (int nj = 0; nj < 4; nj++) {
                    const int g = nj >> 1, p = (nj & 1) * 2;
                    mma16816h(acc[mi][nj], a, bf[g][p], bf[g][p + 1]);
                }
            }
        }
    }

    const int qr = lane >> 2, qc = (lane & 3) * 2;
#pragma unroll
    for (int mi = 0; mi < 4; mi++) {
        const size_t gr = (size_t)(brow + wm + mi * 16 + qr);
#pragma unroll
        for (int nj = 0; nj < 4; nj++) {
            const int gc = bcol + wn + nj * 8 + qc;
            const float2 b2 = *(const float2*)(bias + gc);
            if (MODE == 0 || MODE == 2) {
                float2 o0, o1;
                o0.x = acc[mi][nj][0] + b2.x;
                o0.y = acc[mi][nj][1] + b2.y;
                o1.x = acc[mi][nj][2] + b2.x;
                o1.y = acc[mi][nj][3] + b2.y;
                if (MODE == 2) {
                    const float2 r0 = *(const float2*)(R + gr * N + gc);
                    const float2 r1 = *(const float2*)(R + (gr + 8) * N + gc);
                    o0.x += r0.x; o0.y += r0.y;
                    o1.x += r1.x; o1.y += r1.y;
                }
                *(float2*)(C + gr * N + gc)       = o0;
                *(float2*)(C + (gr + 8) * N + gc) = o1;
            } else if (MODE == 3) {
                const __half2 o0 = __floats2half2_rn(acc[mi][nj][0] + b2.x,
                                                     acc[mi][nj][1] + b2.y);
                const __half2 o1 = __floats2half2_rn(acc[mi][nj][2] + b2.x,
                                                     acc[mi][nj][3] + b2.y);
                *(__half2*)(Of + gr * N + gc)       = o0;
                *(__half2*)(Of + (gr + 8) * N + gc) = o1;
            } else {
                const float h1v0 = acc[mi][nj][0] + b2.x;
                const float hg0  = acc[mi][nj][1] + b2.y;
                const float h1v1 = acc[mi][nj][2] + b2.x;
                const float hg1  = acc[mi][nj][3] + b2.y;
                const float o0 = h1v0 / (1.f + ex2f(-hg0 * L2E));
                const float o1 = h1v1 / (1.f + ex2f(-hg1 * L2E));
                const size_t co = (size_t)(gc >> 1);
                Of[gr * (N >> 1) + co]       = __float2half(o0);
                Of[(gr + 8) * (N >> 1) + co] = __float2half(o1);
            }
        }
    }
#undef LOAD_STAGE
}

// =================== fp16 flash attention ===================
#define ATT_Q 0
#define ATT_KV0 18432
#define ATT_KV1 36864
#define ATT_SMEM 55296

__global__ __launch_bounds__(256, 2)
void attention_f16(const __half* __restrict__ QKVF, const float* __restrict__ PB,
                   __half* __restrict__ CTXF) {
    extern __shared__ char smem[];
    const uint32_t sbase = smem_u32(smem);
    const int tid = threadIdx.x;
    const int wid = tid >> 5, lane = tid & 31;
    const int b = blockIdx.y >> 4, h = blockIdx.y & 15;
    const int q0 = blockIdx.x * 128;
    const int wr = wid * 16;

#pragma unroll
    for (int it = 0; it < 4; it++) {
        const int c = tid + it * 256;
        const int r = c >> 3, co = c & 7;
        cp16(sbase + ATT_Q + (uint32_t)(r * 144 + co * 16),
             QKVF + (((size_t)b << 10) + q0 + r) * 4096 + h * 64 + co * 8);
    }
#define LOAD_KV(kt, bufoff) do {                                              \
        _Pragma("unroll")                                                     \
        for (int it = 0; it < 4; it++) {                                      \
            const int c = tid + it * 256;                                     \
            const int kv = c >> 9;                                            \
            const int cc = c & 511;                                           \
            const int r = cc >> 3, co = cc & 7;                               \
            cp16(sbase + (bufoff) + (uint32_t)(kv * 9216 + r * 144 + co * 16),\
                 QKVF + (((size_t)b << 10) + (kt) * 64 + r) * 4096 +          \
                     (1 + kv) * 1024 + h * 64 + co * 8);                      \
        }                                                                     \
    } while (0)

    LOAD_KV(0, ATT_KV0);
    CP_COMMIT();

    const uint32_t a_lrow = (uint32_t)(lane & 15);
    const uint32_t a_koff2 = (uint32_t)((lane & 16) >> 1) * 2;
    const uint32_t b_lrow = (uint32_t)((lane & 7) + ((lane & 16) >> 1));
    const uint32_t b_koff2 = (uint32_t)(lane & 8) * 2;
    const uint32_t v_row = (uint32_t)((lane & 7) + (lane & 8));
    const uint32_t v_col2 = (uint32_t)((lane & 16) >> 1) * 2;

    const int qr = lane >> 2, qc = (lane & 3) * 2;
    float m0 = -1e30f, m1 = -1e30f, l0 = 0.f, l1 = 0.f;
    float oacc[8][4];
#pragma unroll
    for (int nt = 0; nt < 8; nt++)
#pragma unroll
        for (int e = 0; e < 4; e++) oacc[nt][e] = 0.f;

    for (int kt = 0; kt < 16; kt++) {
        CP_WAIT0();
        __syncthreads();
        const uint32_t kvb = (kt & 1) ? ATT_KV1 : ATT_KV0;
        if (kt < 15) LOAD_KV(kt + 1, (kt & 1) ? ATT_KV0 : ATT_KV1);
        CP_COMMIT();

        float sa[8][4];
#pragma unroll
        for (int nt = 0; nt < 8; nt++)
#pragma unroll
            for (int e = 0; e < 4; e++) sa[nt][e] = 0.f;

#pragma unroll
        for (int k16 = 0; k16 < 4; k16++) {
            uint32_t q[4];
            const uint32_t qaddr =
                sbase + ATT_Q + (uint32_t)(wr + a_lrow) * 144 + k16 * 32 + a_koff2;
            ldm_x4(q[0], q[1], q[2], q[3], qaddr);
#pragma unroll
            for (int ntp = 0; ntp < 4; ntp++) {
                uint32_t kf[4];
                const uint32_t kaddr =
                    sbase + kvb + (uint32_t)(ntp * 16 + b_lrow) * 144 + k16 * 32 + b_koff2;
                ldm_x4(kf[0], kf[1], kf[2], kf[3], kaddr);
                mma16816h(sa[2 * ntp],     q, kf[0], kf[1]);
                mma16816h(sa[2 * ntp + 1], q, kf[2], kf[3]);
            }
        }

        const size_t r0g = (size_t)(q0 + wr + qr);
        const size_t pb0 = r0g * 1024 + kt * 64 + qc;
        const size_t pb1 = (r0g + 8) * 1024 + kt * 64 + qc;
#pragma unroll
        for (int nt = 0; nt < 8; nt++) {
            const float2 p0 = *(const float2*)&PB[pb0 + nt * 8];
            const float2 p1 = *(const float2*)&PB[pb1 + nt * 8];
            sa[nt][0] = sa[nt][0] * 0.125f + p0.x;
            sa[nt][1] = sa[nt][1] * 0.125f + p0.y;
            sa[nt][2] = sa[nt][2] * 0.125f + p1.x;
            sa[nt][3] = sa[nt][3] * 0.125f + p1.y;
        }

        float tm0 = -1e30f, tm1 = -1e30f;
#pragma unroll
        for (int nt = 0; nt < 8; nt++) {
            tm0 = fmaxf(tm0, fmaxf(sa[nt][0], sa[nt][1]));
            tm1 = fmaxf(tm1, fmaxf(sa[nt][2], sa[nt][3]));
        }
        tm0 = fmaxf(tm0, __shfl_xor_sync(0xffffffffu, tm0, 1));
        tm0 = fmaxf(tm0, __shfl_xor_sync(0xffffffffu, tm0, 2));
        tm1 = fmaxf(tm1, __shfl_xor_sync(0xffffffffu, tm1, 1));
        tm1 = fmaxf(tm1, __shfl_xor_sync(0xffffffffu, tm1, 2));
        const float mn0 = fmaxf(m0, tm0), mn1 = fmaxf(m1, tm1);
        const float cr0 = ex2f((m0 - mn0) * L2E), cr1 = ex2f((m1 - mn1) * L2E);
        m0 = mn0; m1 = mn1;

        float rs0 = 0.f, rs1 = 0.f;
#pragma unroll
        for (int nt = 0; nt < 8; nt++) {
            sa[nt][0] = ex2f((sa[nt][0] - mn0) * L2E);
            sa[nt][1] = ex2f((sa[nt][1] - mn0) * L2E);
            sa[nt][2] = ex2f((sa[nt][2] - mn1) * L2E);
            sa[nt][3] = ex2f((sa[nt][3] - mn1) * L2E);
            rs0 += sa[nt][0] + sa[nt][1];
            rs1 += sa[nt][2] + sa[nt][3];
        }
        rs0 += __shfl_xor_sync(0xffffffffu, rs0, 1);
        rs0 += __shfl_xor_sync(0xffffffffu, rs0, 2);
        rs1 += __shfl_xor_sync(0xffffffffu, rs1, 1);
        rs1 += __shfl_xor_sync(0xffffffffu, rs1, 2);
        l0 = l0 * cr0 + rs0;
        l1 = l1 * cr1 + rs1;
#pragma unroll
        for (int nt = 0; nt < 8; nt++) {
            oacc[nt][0] *= cr0; oacc[nt][1] *= cr0;
            oacc[nt][2] *= cr1; oacc[nt][3] *= cr1;
        }

#pragma unroll
        for (int j = 0; j < 4; j++) {
            uint32_t pha[4];
            {
                const float* s0 = sa[2 * j];
                const float* s1 = sa[2 * j + 1];
                const __half2 a0 = __floats2half2_rn(s0[0], s0[1]);
                const __half2 a1 = __floats2half2_rn(s0[2], s0[3]);
                const __half2 a2 = __floats2half2_rn(s1[0], s1[1]);
                const __half2 a3 = __floats2half2_rn(s1[2], s1[3]);
                pha[0] = *(const uint32_t*)&a0;
                pha[1] = *(const uint32_t*)&a1;
                pha[2] = *(const uint32_t*)&a2;
                pha[3] = *(const uint32_t*)&a3;
            }
#pragma unroll
            for (int ntp = 0; ntp < 4; ntp++) {
                uint32_t vf[4];
                const uint32_t vaddr = sbase + kvb + 9216 +
                    (uint32_t)(j * 16 + v_row) * 144 + (uint32_t)(ntp * 16) * 2 + v_col2;
                ldm_x4t(vf[0], vf[1], vf[2], vf[3], vaddr);
                mma16816h(oacc[2 * ntp],     pha, vf[0], vf[1]);
                mma16816h(oacc[2 * ntp + 1], pha, vf[2], vf[3]);
            }
        }
        __syncthreads();
    }

    const float inv0 = 1.f / l0, inv1 = 1.f / l1;
    const size_t cr0 = (size_t)((b << 10) + q0 + wr + qr);
    const size_t colb = (size_t)(h * 64 + qc);
#pragma unroll
    for (int nt = 0; nt < 8; nt++) {
        const __half2 h2a = __floats2half2_rn(oacc[nt][0] * inv0, oacc[nt][1] * inv0);
        const __half2 h2b = __floats2half2_rn(oacc[nt][2] * inv1, oacc[nt][3] * inv1);
        *(__half2*)(CTXF + cr0 * 1024 + colb + nt * 8)       = h2a;
        *(__half2*)(CTXF + (cr0 + 8) * 1024 + colb + nt * 8) = h2b;
    }
#undef LOAD_KV
}

// =================== merged prep: ONE launch does everything ===================
// block ranges (each block handles 1024 fp32 elements = 256 threads x float4):
// [0,4096)       posbias (1M outputs, 8 floats read each)
// [4096,8192)    x -> fp16           (4M elements)
// [8192,12288)   Wq/Wk/Wv/Wg -> wqkvg col-packed (4 x 1M)
// [12288,13312)  Wo                  (1M)
// [13312,17408)  Wf1+Wfg interleave  (4M each)
// [17408,21504)  Wf2                 (4M)
// [21504,21552)  bias packing        (12288 scalars)
#define PREP_BLOCKS 21552

__device__ __forceinline__ uint2 f4_to_h4(float4 v) {
    const __half2 a = __floats2half2_rn(v.x, v.y);
    const __half2 b = __floats2half2_rn(v.z, v.w);
    uint2 o;
    o.x = *(const uint32_t*)&a;
    o.y = *(const uint32_t*)&b;
    return o;
}

__global__ __launch_bounds__(256)
void prep_all(const float* __restrict__ pe, float* __restrict__ pb,
              const float* __restrict__ x, __half* __restrict__ xf,
              const float* __restrict__ Wq, const float* __restrict__ Wk,
              const float* __restrict__ Wv, const float* __restrict__ Wg,
              const float* __restrict__ Wo_, const float* __restrict__ Wf1,
              const float* __restrict__ Wfg, const float* __restrict__ Wf2,
              __half* __restrict__ wq, __half* __restrict__ wo,
              __half* __restrict__ wff, __half* __restrict__ w2,
              const float* __restrict__ bq, const float* __restrict__ bk,
              const float* __restrict__ bv, const float* __restrict__ bg,
              const float* __restrict__ bf1, const float* __restrict__ bfg,
              float* __restrict__ biasq, float* __restrict__ biasf) {
    const int blk = blockIdx.x;
    const int t = threadIdx.x;

    if (blk < 4096) {                      // pos bias mean
        const size_t i = (size_t)blk * 256 + t;
        const float4 a = *(const float4*)&pe[i * 8];
        const float4 b = *(const float4*)&pe[i * 8 + 4];
        pb[i] = (a.x + a.y + a.z + a.w + b.x + b.y + b.z + b.w) * 0.125f;
    } else if (blk < 8192) {               // x -> fp16 (4M elements)
        const size_t i = ((size_t)(blk - 4096) * 256 + t) * 4;
        *(uint2*)(xf + i) = f4_to_h4(*(const float4*)(x + i));
    } else if (blk < 12288) {              // QKVG weights, col-packed into [1024,4096]
        const int w = (blk - 8192) >> 10;
        const float* W = (w == 0) ? Wq : (w == 1) ? Wk : (w == 2) ? Wv : Wg;
        const size_t i = ((size_t)((blk - 8192) & 1023) * 256 + t) * 4;
        const size_t r = i >> 10;
        const int c = (int)(i & 1023);
        *(uint2*)(wq + r * 4096 + w * 1024 + c) = f4_to_h4(*(const float4*)(W + i));
    } else if (blk < 13312) {              // Wo (1M)
        const size_t i = ((size_t)(blk - 12288) * 256 + t) * 4;
        *(uint2*)(wo + i) = f4_to_h4(*(const float4*)(Wo_ + i));
    } else if (blk < 17408) {              // Wf1/Wfg interleave (4M each)
        const size_t i = ((size_t)(blk - 13312) * 256 + t) * 4;
        const float4 a = *(const float4*)(Wf1 + i);
        const float4 g = *(const float4*)(Wfg + i);
        uint4 o;
        const __half2 p0 = __floats2half2_rn(a.x, g.x);
        const __half2 p1 = __floats2half2_rn(a.y, g.y);
        const __half2 p2 = __floats2half2_rn(a.z, g.z);
        const __half2 p3 = __floats2half2_rn(a.w, g.w);
        o.x = *(const uint32_t*)&p0;
        o.y = *(const uint32_t*)&p1;
        o.z = *(const uint32_t*)&p2;
        o.w = *(const uint32_t*)&p3;
        *(uint4*)(wff + i * 2) = o;
    } else if (blk < 21504) {              // Wf2 (4M)
        const size_t i = ((size_t)(blk - 17408) * 256 + t) * 4;
        *(uint2*)(w2 + i) = f4_to_h4(*(const float4*)(Wf2 + i));
    } else {                               // bias packing
        const int i = (blk - 21504) * 256 + t;   // 0..12287
        if (i < 1024) biasq[i] = bq[i];
        else if (i < 2048) biasq[i] = bk[i - 1024];
        else if (i < 3072) biasq[i] = bv[i - 2048];
        else if (i < 4096) biasq[i] = bg[i - 3072];
        else if (i < 8192) biasf[2 * (i - 4096)] = bf1[i - 4096];
        else biasf[2 * (i - 8192) + 1] = bfg[i - 8192];
    }
}

// ---------------- LN1 ----------------
__global__ __launch_bounds__(256)
void ln1_kernel(const float* __restrict__ x, const float* __restrict__ attn,
                const __half* __restrict__ qkvgf, const float* __restrict__ gw,
                const float* __restrict__ gb, float* __restrict__ x1,
                __half* __restrict__ x1f) {
    const size_t base = (size_t)blockIdx.x * E_DIM;
    const size_t gbase = (size_t)blockIdx.x * 4096 + 3072;
    const int t = threadIdx.x;
    float vals[4];
    float s = 0.f, s2 = 0.f;
#pragma unroll
    for (int i = 0; i < 4; i++) {
        const int c = t + i * 256;
        const float gp = __half2float(qkvgf[gbase + c]);
        const float sg = 1.f / (1.f + __expf(-gp));
        const float val = x[base + c] + attn[base + c] * sg;
        vals[i] = val; s += val; s2 += val * val;
    }
    __shared__ float rsm[8], rs2[8];
#pragma unroll
    for (int o = 16; o; o >>= 1) {
        s  += __shfl_xor_sync(0xffffffffu, s,  o);
        s2 += __shfl_xor_sync(0xffffffffu, s2, o);
    }
    if ((t & 31) == 0) { rsm[t >> 5] = s; rs2[t >> 5] = s2; }
    __syncthreads();
    float S = 0.f, S2 = 0.f;
#pragma unroll
    for (int i = 0; i < 8; i++) { S += rsm[i]; S2 += rs2[i]; }
    const float mean = S * (1.f / E_DIM);
    const float var = S2 * (1.f / E_DIM) - mean * mean;
    const float inv = rsqrtf(var + 1e-6f);
#pragma unroll
    for (int i = 0; i < 4; i++) {
        const int c = t + i * 256;
        const float v = (vals[i] - mean) * inv * gw[c] + gb[c];
        x1[base + c] = v;
        x1f[base + c] = __float2half(v);
    }
}

// ---------------- LN2 (input already contains x1+ff residual) ----------------
__global__ __launch_bounds__(256)
void ln2_kernel(const float* __restrict__ ff,
                const float* __restrict__ gw, const float* __restrict__ gb,
                float* __restrict__ out) {
    const size_t base = (size_t)blockIdx.x * E_DIM;
    const int t = threadIdx.x;
    float vals[4];
    float s = 0.f, s2 = 0.f;
#pragma unroll
    for (int i = 0; i < 4; i++) {
        const int c = t + i * 256;
        const float val = ff[base + c];
        vals[i] = val; s += val; s2 += val * val;
    }
    __shared__ float rsm[8], rs2[8];
#pragma unroll
    for (int o = 16; o; o >>= 1) {
        s  += __shfl_xor_sync(0xffffffffu, s,  o);
        s2 += __shfl_xor_sync(0xffffffffu, s2, o);
    }
    if ((t & 31) == 0) { rsm[t >> 5] = s; rs2[t >> 5] = s2; }
    __syncthreads();
    float S = 0.f, S2 = 0.f;
#pragma unroll
    for (int i = 0; i < 8; i++) { S += rsm[i]; S2 += rs2[i]; }
    const float mean = S * (1.f / E_DIM);
    const float var = S2 * (1.f / E_DIM) - mean * mean;
    const float inv = rsqrtf(var + 1e-6f);
#pragma unroll
    for (int i = 0; i < 4; i++) {
        const int c = t + i * 256;
        out[base + c] = (vals[i] - mean) * inv * gw[c] + gb[c];
    }
}

// =================== launch ===================
extern "C" void kernel_launch(void* const* d_in, const int* in_sizes, int n_in,
                              void* d_out, int out_size) {
    const float* x   = (const float*)d_in[0];
    const float* pe  = (const float*)d_in[1];
    const float* Wq  = (const float*)d_in[2];
    const float* bq  = (const float*)d_in[3];
    const float* Wk  = (const float*)d_in[4];
    const float* bk  = (const float*)d_in[5];
    const float* Wv  = (const float*)d_in[6];
    const float* bv  = (const float*)d_in[7];
    const float* Wo  = (const float*)d_in[8];
    const float* bo  = (const float*)d_in[9];
    const float* Wg  = (const float*)d_in[10];
    const float* bg  = (const float*)d_in[11];
    const float* Wf1 = (const float*)d_in[12];
    const float* bf1 = (const float*)d_in[13];
    const float* Wfg = (const float*)d_in[14];
    const float* bfg = (const float*)d_in[15];
    const float* Wf2 = (const float*)d_in[16];
    const float* bf2 = (const float*)d_in[17];
    const float* l1g = (const float*)d_in[18];
    const float* l1b = (const float*)d_in[19];
    const float* l2g = (const float*)d_in[20];
    const float* l2b = (const float*)d_in[21];
    float* out = (float*)d_out;

    float *tmp, *x1, *pb, *biasq, *biasf;
    __half *qkvgf, *xf, *ctxf, *x1f, *h1f;
    __half *wq, *wo, *wff, *w2;
    cudaGetSymbolAddress((void**)&tmp, g_tmp);
    cudaGetSymbolAddress((void**)&x1, g_x1);
    cudaGetSymbolAddress((void**)&pb, g_pb);
    cudaGetSymbolAddress((void**)&biasq, g_bias_qkvg);
    cudaGetSymbolAddress((void**)&biasf, g_bias_ff);
    cudaGetSymbolAddress((void**)&qkvgf, g_qkvgf);
    cudaGetSymbolAddress((void**)&xf, g_xf);
    cudaGetSymbolAddress((void**)&ctxf, g_ctxf);
    cudaGetSymbolAddress((void**)&x1f, g_x1f);
    cudaGetSymbolAddress((void**)&h1f, g_h1f);
    cudaGetSymbolAddress((void**)&wq, g_wqkvg);
    cudaGetSymbolAddress((void**)&wo, g_wo);
    cudaGetSymbolAddress((void**)&wff, g_wff);
    cudaGetSymbolAddress((void**)&w2, g_wf2);

    cudaFuncSetAttribute(attention_f16,
                         cudaFuncAttributeMaxDynamicSharedMemorySize, ATT_SMEM);
    cudaFuncSetAttribute(hmma_gemm<0>,
                         cudaFuncAttributeMaxDynamicSharedMemorySize, GEMM_SMEM);
    cudaFuncSetAttribute(hmma_gemm<1>,
                         cudaFuncAttributeMaxDynamicSharedMemorySize, GEMM_SMEM);
    cudaFuncSetAttribute(hmma_gemm<2>,
                         cudaFuncAttributeMaxDynamicSharedMemorySize, GEMM_SMEM);
    cudaFuncSetAttribute(hmma_gemm<3>,
                         cudaFuncAttributeMaxDynamicSharedMemorySize, GEMM_SMEM);

    // --- single merged prep launch ---
    prep_all<<<PREP_BLOCKS, 256>>>(pe, pb, x, xf,
                                   Wq, Wk, Wv, Wg, Wo, Wf1, Wfg, Wf2,
                                   wq, wo, wff, w2,
                                   bq, bk, bv, bg, bf1, bfg, biasq, biasf);

    // --- QKV + gate projection (fp16 output) ---
    hmma_gemm<3><<<dim3(32, 32), 256, GEMM_SMEM>>>(xf, wq, biasq, nullptr,
                                                   qkvgf, nullptr,
                                                   M_ROWS, 4096, 1024);
    // --- fp16 flash attention ---
    attention_f16<<<dim3(8, 64), 256, ATT_SMEM>>>(qkvgf, pb, ctxf);
    // --- output projection ---
    hmma_gemm<0><<<dim3(8, 32), 256, GEMM_SMEM>>>(ctxf, wo, bo, tmp,
                                                  nullptr, nullptr,
                                                  M_ROWS, 1024, 1024);
    // --- gate + residual + LN1 ---
    ln1_kernel<<<M_ROWS, 256>>>(x, tmp, qkvgf, l1g, l1b, x1, x1f);
    // --- FFN up with fused SwiGLU epilogue ---
    hmma_gemm<1><<<dim3(64, 32), 256, GEMM_SMEM>>>(x1f, wff, biasf, nullptr,
                                                   h1f, nullptr,
                                                   M_ROWS, 8192, 1024);
    // --- FFN down + fused residual add (tmp = x1 + ff) ---
    hmma_gemm<2><<<dim3(8, 32), 256, GEMM_SMEM>>>(h1f, w2, bf2, tmp,
                                                  nullptr, x1,
                                                  M_ROWS, 1024, 4096);
    // --- LN2 ---
    ln2_kernel<<<M_ROWS, 256>>>(tmp, l2g, l2b, out);
}

// round 13
// speedup vs baseline: 1.0625x; 1.0050x over previous
#include <cuda_runtime.h>
#include <cuda_fp16.h>
#include <cstdint>
#include <cstddef>

// Problem constants
#define E_DIM 1024
#define S_LEN 1024
#define B_SZ 4
#define NH 16
#define HD 64
#define FF_DIM 4096
#define M_ROWS (B_SZ * S_LEN)   // 4096

// ---------------- scratch (static device globals; no allocation) ----------------
__device__ float g_tmp[M_ROWS * E_DIM];          // attn_out, later (x1+ff)
__device__ float g_x1[M_ROWS * E_DIM];
__device__ float g_pb[S_LEN * S_LEN];

// fp16 activations
__device__ __half g_qkvgf[M_ROWS * 4096];        // [q|k|v|gate] fp16
__device__ __half g_xf[M_ROWS * E_DIM];
__device__ __half g_ctxf[M_ROWS * E_DIM];
__device__ __half g_x1f[M_ROWS * E_DIM];
__device__ __half g_h1f[(size_t)M_ROWS * FF_DIM];

// fp16 weights in ORIGINAL [K,N] layout (B fed via ldmatrix.trans)
__device__ __half g_wqkvg[1024 * 4096];          // cols: [Wq|Wk|Wv|Wg]
__device__ __half g_wo[1024 * 1024];
__device__ __half g_wff[1024 * 8192];            // cols interleaved: 2n = Wf1_n, 2n+1 = Wfg_n
__device__ __half g_wf2[4096 * 1024];

__device__ float g_bias_qkvg[4096];
__device__ float g_bias_ff[8192];                 // interleaved bf1/bfg

#define L2E 1.4426950408889634f

// =================== PTX helpers (baseline sm_80+ features only) ===================
__device__ __forceinline__ uint32_t smem_u32(const void* p) {
    uint32_t a;
    asm("{ .reg .u64 t; cvta.to.shared.u64 t, %1; cvt.u32.u64 %0, t; }" : "=r"(a) : "l"(p));
    return a;
}
__device__ __forceinline__ void cp16(uint32_t dst, const void* src) {
    asm volatile("cp.async.cg.shared.global [%0], [%1], 16;" :: "r"(dst), "l"(src));
}
#define CP_COMMIT() asm volatile("cp.async.commit_group;" ::: "memory")
#define CP_WAIT1()  asm volatile("cp.async.wait_group 1;" ::: "memory")
#define CP_WAIT0()  asm volatile("cp.async.wait_group 0;" ::: "memory")

__device__ __forceinline__ void ldm_x4(uint32_t& r0, uint32_t& r1, uint32_t& r2,
                                       uint32_t& r3, uint32_t addr) {
    asm volatile("ldmatrix.sync.aligned.m8n8.x4.shared.b16 {%0,%1,%2,%3}, [%4];"
                 : "=r"(r0), "=r"(r1), "=r"(r2), "=r"(r3) : "r"(addr));
}
__device__ __forceinline__ void ldm_x4t(uint32_t& r0, uint32_t& r1, uint32_t& r2,
                                        uint32_t& r3, uint32_t addr) {
    asm volatile("ldmatrix.sync.aligned.m8n8.x4.trans.shared.b16 {%0,%1,%2,%3}, [%4];"
                 : "=r"(r0), "=r"(r1), "=r"(r2), "=r"(r3) : "r"(addr));
}
// fp16 MMA
__device__ __forceinline__ void mma16816h(float* c, const uint32_t* a,
                                          uint32_t b0, uint32_t b1) {
    asm volatile(
        "mma.sync.aligned.m16n8k16.row.col.f32.f16.f16.f32 "
        "{%0,%1,%2,%3}, {%4,%5,%6,%7}, {%8,%9}, {%0,%1,%2,%3};"
        : "+f"(c[0]), "+f"(c[1]), "+f"(c[2]), "+f"(c[3])
        : "r"(a[0]), "r"(a[1]), "r"(a[2]), "r"(a[3]), "r"(b0), "r"(b1));
}
__device__ __forceinline__ float ex2f(float x) {
    float y;
    asm("ex2.approx.ftz.f32 %0, %1;" : "=f"(y) : "f"(x));
    return y;
}

// =================== HMMA GEMM (fp16, BK=64, fragment-pipelined) ===================
// A: [M,K] fp16. W: [K,N] fp16 (original layout).
// MODE 0: C[M,N] fp32 = A@W + bias
// MODE 1: SwiGLU: Of[M,N/2] fp16 = (c_even+b_even) * sigmoid(c_odd+b_odd)
// MODE 2: C = A@W + bias + R
// MODE 3: Of[M,N] fp16 = A@W + bias
// smem stage: A[128r x 144B] @0 (18432B), B[64k x 272B] @18432 (17408B); 3 stages.
#define B_SOFF 18432
#define STAGE_BYTES 35840
#define GEMM_SMEM (3 * STAGE_BYTES)

template <int MODE>
__global__ __launch_bounds__(256, 2)
void hmma_gemm(const __half* __restrict__ Af, const __half* __restrict__ W,
               const float* __restrict__ bias, float* __restrict__ C,
               __half* __restrict__ Of, const float* __restrict__ R,
               int M, int N, int K) {
    extern __shared__ char smem[];
    const uint32_t sb = smem_u32(smem);
    const int tid = threadIdx.x;
    const int wid = tid >> 5, lane = tid & 31;
    const int brow = blockIdx.y * 128, bcol = blockIdx.x * 128;
    const int wm = (wid >> 2) * 64, wn = (wid & 3) * 32;
    const int nst = K >> 6;    // BK=64

#define LOAD_STAGE(s, buf) do {                                                 \
        const uint32_t stb_ = sb + (buf) * STAGE_BYTES;                         \
        _Pragma("unroll")                                                       \
        for (int it_ = 0; it_ < 4; it_++) {                                     \
            const int ca_ = tid + it_ * 256;                                    \
            const int ra_ = ca_ >> 3, cca_ = ca_ & 7;                           \
            cp16(stb_ + (uint32_t)(ra_ * 144 + cca_ * 16),                      \
                 Af + (size_t)(brow + ra_) * K + (s) * 64 + cca_ * 8);          \
            const int rb_ = ca_ >> 4, ccb_ = ca_ & 15;                          \
            cp16(stb_ + (uint32_t)(B_SOFF + rb_ * 272 + ccb_ * 16),             \
                 W + (size_t)((s) * 64 + rb_) * N + bcol + ccb_ * 8);           \
        }                                                                       \
    } while (0)

    float acc[4][4][4];
#pragma unroll
    for (int i = 0; i < 4; i++)
#pragma unroll
        for (int j = 0; j < 4; j++)
#pragma unroll
            for (int r = 0; r < 4; r++) acc[i][j][r] = 0.f;

    LOAD_STAGE(0, 0); CP_COMMIT();
    LOAD_STAGE(1, 1); CP_COMMIT();

    const uint32_t a_lrow = (uint32_t)(lane & 15);
    const uint32_t a_koff = (uint32_t)((lane & 16) >> 1);
    const uint32_t b_krow = (uint32_t)((lane & 7) + (lane & 8));
    const uint32_t b_noff2 = (uint32_t)((lane & 16) >> 1) * 2;

    // B-fragment addresses per k16 index within a stage
#define B_ADDR(stb_, kk_, ni_) \
    ((stb_) + B_SOFF + (uint32_t)((kk_) + b_krow) * 272 + \
     (uint32_t)(wn + (ni_) * 16) * 2 + b_noff2)

    for (int s = 0; s < nst; s++) {
        CP_WAIT1();
        __syncthreads();
        if (s + 2 < nst) LOAD_STAGE(s + 2, (s + 2) % 3);
        CP_COMMIT();
        const uint32_t stb = sb + (uint32_t)(s % 3) * STAGE_BYTES;

        // prime B fragments for kk=0
        uint32_t bcur[2][4], bnxt[2][4];
        ldm_x4t(bcur[0][0], bcur[0][1], bcur[0][2], bcur[0][3], B_ADDR(stb, 0, 0));
        ldm_x4t(bcur[1][0], bcur[1][1], bcur[1][2], bcur[1][3], B_ADDR(stb, 0, 1));

#pragma unroll
        for (int kk = 0; kk < 64; kk += 16) {
            // batched A loads (MLP=4)
            uint32_t a[4][4];
            const uint32_t akcol = (uint32_t)kk + a_koff;
#pragma unroll
            for (int mi = 0; mi < 4; mi++) {
                const uint32_t addr =
                    stb + (uint32_t)(wm + mi * 16 + a_lrow) * 144 + akcol * 2;
                ldm_x4(a[mi][0], a[mi][1], a[mi][2], a[mi][3], addr);
            }
            // prefetch next k16's B fragments into alt regs (hidden under MMAs)
            if (kk < 48) {
                ldm_x4t(bnxt[0][0], bnxt[0][1], bnxt[0][2], bnxt[0][3],
                        B_ADDR(stb, kk + 16, 0));
                ldm_x4t(bnxt[1][0], bnxt[1][1], bnxt[1][2], bnxt[1][3],
                        B_ADDR(stb, kk + 16, 1));
            }
#pragma unroll
            for (int mi = 0; mi < 4; mi++)
#pragma unroll
                for (int nj = 0; nj < 4; nj++) {
                    const int g = nj >> 1, p = (nj & 1) * 2;
                    mma16816h(acc[mi][nj], a[mi], bcur[g][p], bcur[g][p + 1]);
                }
            // rotate B buffers
#pragma unroll
            for (int g = 0; g < 2; g++)
#pragma unroll
                for (int e = 0; e < 4; e++) bcur[g][e] = bnxt[g][e];
        }
    }

    const int qr = lane >> 2, qc = (lane & 3) * 2;
#pragma unroll
    for (int mi = 0; mi < 4; mi++) {
        const size_t gr = (size_t)(brow + wm + mi * 16 + qr);
#pragma unroll
        for (int nj = 0; nj < 4; nj++) {
            const int gc = bcol + wn + nj * 8 + qc;
            const float2 b2 = *(const float2*)(bias + gc);
            if (MODE == 0 || MODE == 2) {
                float2 o0, o1;
                o0.x = acc[mi][nj][0] + b2.x;
                o0.y = acc[mi][nj][1] + b2.y;
                o1.x = acc[mi][nj][2] + b2.x;
                o1.y = acc[mi][nj][3] + b2.y;
                if (MODE == 2) {
                    const float2 r0 = *(const float2*)(R + gr * N + gc);
                    const float2 r1 = *(const float2*)(R + (gr + 8) * N + gc);
                    o0.x += r0.x; o0.y += r0.y;
                    o1.x += r1.x; o1.y += r1.y;
                }
                *(float2*)(C + gr * N + gc)       = o0;
                *(float2*)(C + (gr + 8) * N + gc) = o1;
            } else if (MODE == 3) {
                const __half2 o0 = __floats2half2_rn(acc[mi][nj][0] + b2.x,
                                                     acc[mi][nj][1] + b2.y);
                const __half2 o1 = __floats2half2_rn(acc[mi][nj][2] + b2.x,
                                                     acc[mi][nj][3] + b2.y);
                *(__half2*)(Of + gr * N + gc)       = o0;
                *(__half2*)(Of + (gr + 8) * N + gc) = o1;
            } else {
                const float h1v0 = acc[mi][nj][0] + b2.x;
                const float hg0  = acc[mi][nj][1] + b2.y;
                const float h1v1 = acc[mi][nj][2] + b2.x;
                const float hg1  = acc[mi][nj][3] + b2.y;
                const float o0 = h1v0 / (1.f + ex2f(-hg0 * L2E));
                const float o1 = h1v1 / (1.f + ex2f(-hg1 * L2E));
                const size_t co = (size_t)(gc >> 1);
                Of[gr * (N >> 1) + co]       = __float2half(o0);
                Of[(gr + 8) * (N >> 1) + co] = __float2half(o1);
            }
        }
    }
#undef LOAD_STAGE
#undef B_ADDR
}

// =================== fp16 flash attention ===================
#define ATT_Q 0
#define ATT_KV0 18432
#define ATT_KV1 36864
#define ATT_SMEM 55296

__global__ __launch_bounds__(256, 2)
void attention_f16(const __half* __restrict__ QKVF, const float* __restrict__ PB,
                   __half* __restrict__ CTXF) {
    extern __shared__ char smem[];
    const uint32_t sbase = smem_u32(smem);
    const int tid = threadIdx.x;
    const int wid = tid >> 5, lane = tid & 31;
    const int b = blockIdx.y >> 4, h = blockIdx.y & 15;
    const int q0 = blockIdx.x * 128;
    const int wr = wid * 16;

#pragma unroll
    for (int it = 0; it < 4; it++) {
        const int c = tid + it * 256;
        const int r = c >> 3, co = c & 7;
        cp16(sbase + ATT_Q + (uint32_t)(r * 144 + co * 16),
             QKVF + (((size_t)b << 10) + q0 + r) * 4096 + h * 64 + co * 8);
    }
#define LOAD_KV(kt, bufoff) do {                                              \
        _Pragma("unroll")                                                     \
        for (int it = 0; it < 4; it++) {                                      \
            const int c = tid + it * 256;                                     \
            const int kv = c >> 9;                                            \
            const int cc = c & 511;                                           \
            const int r = cc >> 3, co = cc & 7;                               \
            cp16(sbase + (bufoff) + (uint32_t)(kv * 9216 + r * 144 + co * 16),\
                 QKVF + (((size_t)b << 10) + (kt) * 64 + r) * 4096 +          \
                     (1 + kv) * 1024 + h * 64 + co * 8);                      \
        }                                                                     \
    } while (0)

    LOAD_KV(0, ATT_KV0);
    CP_COMMIT();

    const uint32_t a_lrow = (uint32_t)(lane & 15);
    const uint32_t a_koff2 = (uint32_t)((lane & 16) >> 1) * 2;
    const uint32_t b_lrow = (uint32_t)((lane & 7) + ((lane & 16) >> 1));
    const uint32_t b_koff2 = (uint32_t)(lane & 8) * 2;
    const uint32_t v_row = (uint32_t)((lane & 7) + (lane & 8));
    const uint32_t v_col2 = (uint32_t)((lane & 16) >> 1) * 2;

    const int qr = lane >> 2, qc = (lane & 3) * 2;
    float m0 = -1e30f, m1 = -1e30f, l0 = 0.f, l1 = 0.f;
    float oacc[8][4];
#pragma unroll
    for (int nt = 0; nt < 8; nt++)
#pragma unroll
        for (int e = 0; e < 4; e++) oacc[nt][e] = 0.f;

    for (int kt = 0; kt < 16; kt++) {
        CP_WAIT0();
        __syncthreads();
        const uint32_t kvb = (kt & 1) ? ATT_KV1 : ATT_KV0;
        if (kt < 15) LOAD_KV(kt + 1, (kt & 1) ? ATT_KV0 : ATT_KV1);
        CP_COMMIT();

        float sa[8][4];
#pragma unroll
        for (int nt = 0; nt < 8; nt++)
#pragma unroll
            for (int e = 0; e < 4; e++) sa[nt][e] = 0.f;

#pragma unroll
        for (int k16 = 0; k16 < 4; k16++) {
            uint32_t q[4];
            const uint32_t qaddr =
                sbase + ATT_Q + (uint32_t)(wr + a_lrow) * 144 + k16 * 32 + a_koff2;
            ldm_x4(q[0], q[1], q[2], q[3], qaddr);
#pragma unroll
            for (int ntp = 0; ntp < 4; ntp++) {
                uint32_t kf[4];
                const uint32_t kaddr =
                    sbase + kvb + (uint32_t)(ntp * 16 + b_lrow) * 144 + k16 * 32 + b_koff2;
                ldm_x4(kf[0], kf[1], kf[2], kf[3], kaddr);
                mma16816h(sa[2 * ntp],     q, kf[0], kf[1]);
                mma16816h(sa[2 * ntp + 1], q, kf[2], kf[3]);
            }
        }

        const size_t r0g = (size_t)(q0 + wr + qr);
        const size_t pb0 = r0g * 1024 + kt * 64 + qc;
        const size_t pb1 = (r0g + 8) * 1024 + kt * 64 + qc;
#pragma unroll
        for (int nt = 0; nt < 8; nt++) {
            const float2 p0 = *(const float2*)&PB[pb0 + nt * 8];
            const float2 p1 = *(const float2*)&PB[pb1 + nt * 8];
            sa[nt][0] = sa[nt][0] * 0.125f + p0.x;
            sa[nt][1] = sa[nt][1] * 0.125f + p0.y;
            sa[nt][2] = sa[nt][2] * 0.125f + p1.x;
            sa[nt][3] = sa[nt][3] * 0.125f + p1.y;
        }

        float tm0 = -1e30f, tm1 = -1e30f;
#pragma unroll
        for (int nt = 0; nt < 8; nt++) {
            tm0 = fmaxf(tm0, fmaxf(sa[nt][0], sa[nt][1]));
            tm1 = fmaxf(tm1, fmaxf(sa[nt][2], sa[nt][3]));
        }
        tm0 = fmaxf(tm0, __shfl_xor_sync(0xffffffffu, tm0, 1));
        tm0 = fmaxf(tm0, __shfl_xor_sync(0xffffffffu, tm0, 2));
        tm1 = fmaxf(tm1, __shfl_xor_sync(0xffffffffu, tm1, 1));
        tm1 = fmaxf(tm1, __shfl_xor_sync(0xffffffffu, tm1, 2));
        const float mn0 = fmaxf(m0, tm0), mn1 = fmaxf(m1, tm1);
        const float cr0 = ex2f((m0 - mn0) * L2E), cr1 = ex2f((m1 - mn1) * L2E);
        m0 = mn0; m1 = mn1;

        float rs0 = 0.f, rs1 = 0.f;
#pragma unroll
        for (int nt = 0; nt < 8; nt++) {
            sa[nt][0] = ex2f((sa[nt][0] - mn0) * L2E);
            sa[nt][1] = ex2f((sa[nt][1] - mn0) * L2E);
            sa[nt][2] = ex2f((sa[nt][2] - mn1) * L2E);
            sa[nt][3] = ex2f((sa[nt][3] - mn1) * L2E);
            rs0 += sa[nt][0] + sa[nt][1];
            rs1 += sa[nt][2] + sa[nt][3];
        }
        rs0 += __shfl_xor_sync(0xffffffffu, rs0, 1);
        rs0 += __shfl_xor_sync(0xffffffffu, rs0, 2);
        rs1 += __shfl_xor_sync(0xffffffffu, rs1, 1);
        rs1 += __shfl_xor_sync(0xffffffffu, rs1, 2);
        l0 = l0 * cr0 + rs0;
        l1 = l1 * cr1 + rs1;
#pragma unroll
        for (int nt = 0; nt < 8; nt++) {
            oacc[nt][0] *= cr0; oacc[nt][1] *= cr0;
            oacc[nt][2] *= cr1; oacc[nt][3] *= cr1;
        }

#pragma unroll
        for (int j = 0; j < 4; j++) {
            uint32_t pha[4];
            {
                const float* s0 = sa[2 * j];
                const float* s1 = sa[2 * j + 1];
                const __half2 a0 = __floats2half2_rn(s0[0], s0[1]);
                const __half2 a1 = __floats2half2_rn(s0[2], s0[3]);
                const __half2 a2 = __floats2half2_rn(s1[0], s1[1]);
                const __half2 a3 = __floats2half2_rn(s1[2], s1[3]);
                pha[0] = *(const uint32_t*)&a0;
                pha[1] = *(const uint32_t*)&a1;
                pha[2] = *(const uint32_t*)&a2;
                pha[3] = *(const uint32_t*)&a3;
            }
#pragma unroll
            for (int ntp = 0; ntp < 4; ntp++) {
                uint32_t vf[4];
                const uint32_t vaddr = sbase + kvb + 9216 +
                    (uint32_t)(j * 16 + v_row) * 144 + (uint32_t)(ntp * 16) * 2 + v_col2;
                ldm_x4t(vf[0], vf[1], vf[2], vf[3], vaddr);
                mma16816h(oacc[2 * ntp],     pha, vf[0], vf[1]);
                mma16816h(oacc[2 * ntp + 1], pha, vf[2], vf[3]);
            }
        }
        __syncthreads();
    }

    const float inv0 = 1.f / l0, inv1 = 1.f / l1;
    const size_t cr0 = (size_t)((b << 10) + q0 + wr + qr);
    const size_t colb = (size_t)(h * 64 + qc);
#pragma unroll
    for (int nt = 0; nt < 8; nt++) {
        const __half2 h2a = __floats2half2_rn(oacc[nt][0] * inv0, oacc[nt][1] * inv0);
        const __half2 h2b = __floats2half2_rn(oacc[nt][2] * inv1, oacc[nt][3] * inv1);
        *(__half2*)(CTXF + cr0 * 1024 + colb + nt * 8)       = h2a;
        *(__half2*)(CTXF + (cr0 + 8) * 1024 + colb + nt * 8) = h2b;
    }
#undef LOAD_KV
}

// =================== merged prep: ONE launch does everything ===================
#define PREP_BLOCKS 21552

__device__ __forceinline__ uint2 f4_to_h4(float4 v) {
    const __half2 a = __floats2half2_rn(v.x, v.y);
    const __half2 b = __floats2half2_rn(v.z, v.w);
    uint2 o;
    o.x = *(const uint32_t*)&a;
    o.y = *(const uint32_t*)&b;
    return o;
}

__global__ __launch_bounds__(256)
void prep_all(const float* __restrict__ pe, float* __restrict__ pb,
              const float* __restrict__ x, __half* __restrict__ xf,
              const float* __restrict__ Wq, const float* __restrict__ Wk,
              const float* __restrict__ Wv, const float* __restrict__ Wg,
              const float* __restrict__ Wo_, const float* __restrict__ Wf1,
              const float* __restrict__ Wfg, const float* __restrict__ Wf2,
              __half* __restrict__ wq, __half* __restrict__ wo,
              __half* __restrict__ wff, __half* __restrict__ w2,
              const float* __restrict__ bq, const float* __restrict__ bk,
              const float* __restrict__ bv, const float* __restrict__ bg,
              const float* __restrict__ bf1, const float* __restrict__ bfg,
              float* __restrict__ biasq, float* __restrict__ biasf) {
    const int blk = blockIdx.x;
    const int t = threadIdx.x;

    if (blk < 4096) {
        const size_t i = (size_t)blk * 256 + t;
        const float4 a = *(const float4*)&pe[i * 8];
        const float4 b = *(const float4*)&pe[i * 8 + 4];
        pb[i] = (a.x + a.y + a.z + a.w + b.x + b.y + b.z + b.w) * 0.125f;
    } else if (blk < 8192) {
        const size_t i = ((size_t)(blk - 4096) * 256 + t) * 4;
        *(uint2*)(xf + i) = f4_to_h4(*(const float4*)(x + i));
    } else if (blk < 12288) {
        const int w = (blk - 8192) >> 10;
        const float* W = (w == 0) ? Wq : (w == 1) ? Wk : (w == 2) ? Wv : Wg;
        const size_t i = ((size_t)((blk - 8192) & 1023) * 256 + t) * 4;
        const size_t r = i >> 10;
        const int c = (int)(i & 1023);
        *(uint2*)(wq + r * 4096 + w * 1024 + c) = f4_to_h4(*(const float4*)(W + i));
    } else if (blk < 13312) {
        const size_t i = ((size_t)(blk - 12288) * 256 + t) * 4;
        *(uint2*)(wo + i) = f4_to_h4(*(const float4*)(Wo_ + i));
    } else if (blk < 17408) {
        const size_t i = ((size_t)(blk - 13312) * 256 + t) * 4;
        const float4 a = *(const float4*)(Wf1 + i);
        const float4 g = *(const float4*)(Wfg + i);
        uint4 o;
        const __half2 p0 = __floats2half2_rn(a.x, g.x);
        const __half2 p1 = __floats2half2_rn(a.y, g.y);
        const __half2 p2 = __floats2half2_rn(a.z, g.z);
        const __half2 p3 = __floats2half2_rn(a.w, g.w);
        o.x = *(const uint32_t*)&p0;
        o.y = *(const uint32_t*)&p1;
        o.z = *(const uint32_t*)&p2;
        o.w = *(const uint32_t*)&p3;
        *(uint4*)(wff + i * 2) = o;
    } else if (blk < 21504) {
        const size_t i = ((size_t)(blk - 17408) * 256 + t) * 4;
        *(uint2*)(w2 + i) = f4_to_h4(*(const float4*)(Wf2 + i));
    } else {
        const int i = (blk - 21504) * 256 + t;
        if (i < 1024) biasq[i] = bq[i];
        else if (i < 2048) biasq[i] = bk[i - 1024];
        else if (i < 3072) biasq[i] = bv[i - 2048];
        else if (i < 4096) biasq[i] = bg[i - 3072];
        else if (i < 8192) biasf[2 * (i - 4096)] = bf1[i - 4096];
        else biasf[2 * (i - 8192) + 1] = bfg[i - 8192];
    }
}

// ---------------- LN1 ----------------
__global__ __launch_bounds__(256)
void ln1_kernel(const float* __restrict__ x, const float* __restrict__ attn,
                const __half* __restrict__ qkvgf, const float* __restrict__ gw,
                const float* __restrict__ gb, float* __restrict__ x1,
                __half* __restrict__ x1f) {
    const size_t base = (size_t)blockIdx.x * E_DIM;
    const size_t gbase = (size_t)blockIdx.x * 4096 + 3072;
    const int t = threadIdx.x;
    float vals[4];
    float s = 0.f, s2 = 0.f;
#pragma unroll
    for (int i = 0; i < 4; i++) {
        const int c = t + i * 256;
        const float gp = __half2float(qkvgf[gbase + c]);
        const float sg = 1.f / (1.f + __expf(-gp));
        const float val = x[base + c] + attn[base + c] * sg;
        vals[i] = val; s += val; s2 += val * val;
    }
    __shared__ float rsm[8], rs2[8];
#pragma unroll
    for (int o = 16; o; o >>= 1) {
        s  += __shfl_xor_sync(0xffffffffu, s,  o);
        s2 += __shfl_xor_sync(0xffffffffu, s2, o);
    }
    if ((t & 31) == 0) { rsm[t >> 5] = s; rs2[t >> 5] = s2; }
    __syncthreads();
    float S = 0.f, S2 = 0.f;
#pragma unroll
    for (int i = 0; i < 8; i++) { S += rsm[i]; S2 += rs2[i]; }
    const float mean = S * (1.f / E_DIM);
    const float var = S2 * (1.f / E_DIM) - mean * mean;
    const float inv = rsqrtf(var + 1e-6f);
#pragma unroll
    for (int i = 0; i < 4; i++) {
        const int c = t + i * 256;
        const float v = (vals[i] - mean) * inv * gw[c] + gb[c];
        x1[base + c] = v;
        x1f[base + c] = __float2half(v);
    }
}

// ---------------- LN2 (input already contains x1+ff residual) ----------------
__global__ __launch_bounds__(256)
void ln2_kernel(const float* __restrict__ ff,
                const float* __restrict__ gw, const float* __restrict__ gb,
                float* __restrict__ out) {
    const size_t base = (size_t)blockIdx.x * E_DIM;
    const int t = threadIdx.x;
    float vals[4];
    float s = 0.f, s2 = 0.f;
#pragma unroll
    for (int i = 0; i < 4; i++) {
        const int c = t + i * 256;
        const float val = ff[base + c];
        vals[i] = val; s += val; s2 += val * val;
    }
    __shared__ float rsm[8], rs2[8];
#pragma unroll
    for (int o = 16; o; o >>= 1) {
        s  += __shfl_xor_sync(0xffffffffu, s,  o);
        s2 += __shfl_xor_sync(0xffffffffu, s2, o);
    }
    if ((t & 31) == 0) { rsm[t >> 5] = s; rs2[t >> 5] = s2; }
    __syncthreads();
    float S = 0.f, S2 = 0.f;
#pragma unroll
    for (int i = 0; i < 8; i++) { S += rsm[i]; S2 += rs2[i]; }
    const float mean = S * (1.f / E_DIM);
    const float var = S2 * (1.f / E_DIM) - mean * mean;
    const float inv = rsqrtf(var + 1e-6f);
#pragma unroll
    for (int i = 0; i < 4; i++) {
        const int c = t + i * 256;
        out[base + c] = (vals[i] - mean) * inv * gw[c] + gb[c];
    }
}

// =================== launch ===================
extern "C" void kernel_launch(void* const* d_in, const int* in_sizes, int n_in,
                              void* d_out, int out_size) {
    const float* x   = (const float*)d_in[0];
    const float* pe  = (const float*)d_in[1];
    const float* Wq  = (const float*)d_in[2];
    const float* bq  = (const float*)d_in[3];
    const float* Wk  = (const float*)d_in[4];
    const float* bk  = (const float*)d_in[5];
    const float* Wv  = (const float*)d_in[6];
    const float* bv  = (const float*)d_in[7];
    const float* Wo  = (const float*)d_in[8];
    const float* bo  = (const float*)d_in[9];
    const float* Wg  = (const float*)d_in[10];
    const float* bg  = (const float*)d_in[11];
    const float* Wf1 = (const float*)d_in[12];
    const float* bf1 = (const float*)d_in[13];
    const float* Wfg = (const float*)d_in[14];
    const float* bfg = (const float*)d_in[15];
    const float* Wf2 = (const float*)d_in[16];
    const float* bf2 = (const float*)d_in[17];
    const float* l1g = (const float*)d_in[18];
    const float* l1b = (const float*)d_in[19];
    const float* l2g = (const float*)d_in[20];
    const float* l2b = (const float*)d_in[21];
    float* out = (float*)d_out;

    float *tmp, *x1, *pb, *biasq, *biasf;
    __half *qkvgf, *xf, *ctxf, *x1f, *h1f;
    __half *wq, *wo, *wff, *w2;
    cudaGetSymbolAddress((void**)&tmp, g_tmp);
    cudaGetSymbolAddress((void**)&x1, g_x1);
    cudaGetSymbolAddress((void**)&pb, g_pb);
    cudaGetSymbolAddress((void**)&biasq, g_bias_qkvg);
    cudaGetSymbolAddress((void**)&biasf, g_bias_ff);
    cudaGetSymbolAddress((void**)&qkvgf, g_qkvgf);
    cudaGetSymbolAddress((void**)&xf, g_xf);
    cudaGetSymbolAddress((void**)&ctxf, g_ctxf);
    cudaGetSymbolAddress((void**)&x1f, g_x1f);
    cudaGetSymbolAddress((void**)&h1f, g_h1f);
    cudaGetSymbolAddress((void**)&wq, g_wqkvg);
    cudaGetSymbolAddress((void**)&wo, g_wo);
    cudaGetSymbolAddress((void**)&wff, g_wff);
    cudaGetSymbolAddress((void**)&w2, g_wf2);

    cudaFuncSetAttribute(attention_f16,
                         cudaFuncAttributeMaxDynamicSharedMemorySize, ATT_SMEM);
    cudaFuncSetAttribute(hmma_gemm<0>,
                         cudaFuncAttributeMaxDynamicSharedMemorySize, GEMM_SMEM);
    cudaFuncSetAttribute(hmma_gemm<1>,
                         cudaFuncAttributeMaxDynamicSharedMemorySize, GEMM_SMEM);
    cudaFuncSetAttribute(hmma_gemm<2>,
                         cudaFuncAttributeMaxDynamicSharedMemorySize, GEMM_SMEM);
    cudaFuncSetAttribute(hmma_gemm<3>,
                         cudaFuncAttributeMaxDynamicSharedMemorySize, GEMM_SMEM);

    // --- single merged prep launch ---
    prep_all<<<PREP_BLOCKS, 256>>>(pe, pb, x, xf,
                                   Wq, Wk, Wv, Wg, Wo, Wf1, Wfg, Wf2,
                                   wq, wo, wff, w2,
                                   bq, bk, bv, bg, bf1, bfg, biasq, biasf);

    // --- QKV + gate projection (fp16 output) ---
    hmma_gemm<3><<<dim3(32, 32), 256, GEMM_SMEM>>>(xf, wq, biasq, nullptr,
                                                   qkvgf, nullptr,
                                                   M_ROWS, 4096, 1024);
    // --- fp16 flash attention ---
    attention_f16<<<dim3(8, 64), 256, ATT_SMEM>>>(qkvgf, pb, ctxf);
    // --- output projection ---
    hmma_gemm<0><<<dim3(8, 32), 256, GEMM_SMEM>>>(ctxf, wo, bo, tmp,
                                                  nullptr, nullptr,
                                                  M_ROWS, 1024, 1024);
    // --- gate + residual + LN1 ---
    ln1_kernel<<<M_ROWS, 256>>>(x, tmp, qkvgf, l1g, l1b, x1, x1f);
    // --- FFN up with fused SwiGLU epilogue ---
    hmma_gemm<1><<<dim3(64, 32), 256, GEMM_SMEM>>>(x1f, wff, biasf, nullptr,
                                                   h1f, nullptr,
                                                   M_ROWS, 8192, 1024);
    // --- FFN down + fused residual add (tmp = x1 + ff) ---
    hmma_gemm<2><<<dim3(8, 32), 256, GEMM_SMEM>>>(h1f, w2, bf2, tmp,
                                                  nullptr, x1,
                                                  M_ROWS, 1024, 4096);
    // --- LN2 ---
    ln2_kernel<<<M_ROWS, 256>>>(tmp, l2g, l2b, out);
}